// round 1
// baseline (speedup 1.0000x reference)
#include <cuda_runtime.h>
#include <cuda_bf16.h>
#include <math.h>

// ---------------- problem constants ----------------
#define D_MODEL 768
#define N_HEADS 12
#define D_HEAD  64
#define D_MLP   3072
#define BATCH   2
#define SEQ     2048
#define ROWS    (BATCH*SEQ)          // 4096
#define QKV_N   (3*D_MODEL)          // 2304
#define IGNORE_V (-100000.0f)

// ---------------- device scratch (no runtime alloc allowed) ----------------
__device__ float g_x1    [ROWS * D_MODEL];
__device__ float g_qkv   [ROWS * QKV_N];
__device__ float g_z     [ROWS * D_MODEL];
__device__ float g_mid   [ROWS * D_MODEL];
__device__ float g_x2    [ROWS * D_MODEL];
__device__ float g_hidden[ROWS * D_MLP];
__device__ float g_wqkv  [D_MODEL * QKV_N];
__device__ float g_bqkv  [QKV_N];

// ---------------- helpers ----------------
__device__ __forceinline__ float gelu_new_f(float x) {
    const float c = 0.7978845608028654f;
    float x3 = x * x * x;
    return 0.5f * x * (1.0f + tanhf(c * (x + 0.044715f * x3)));
}

__device__ __forceinline__ float rowred_max16(float v) {
    v = fmaxf(v, __shfl_xor_sync(0xffffffffu, v, 8));
    v = fmaxf(v, __shfl_xor_sync(0xffffffffu, v, 4));
    v = fmaxf(v, __shfl_xor_sync(0xffffffffu, v, 2));
    v = fmaxf(v, __shfl_xor_sync(0xffffffffu, v, 1));
    return v;
}
__device__ __forceinline__ float rowred_sum16(float v) {
    v += __shfl_xor_sync(0xffffffffu, v, 8);
    v += __shfl_xor_sync(0xffffffffu, v, 4);
    v += __shfl_xor_sync(0xffffffffu, v, 2);
    v += __shfl_xor_sync(0xffffffffu, v, 1);
    return v;
}

// block-wide sum for 256 threads
__device__ __forceinline__ float block_sum256(float v) {
    __shared__ float red[8];
    __shared__ float total;
    #pragma unroll
    for (int m = 16; m >= 1; m >>= 1) v += __shfl_xor_sync(0xffffffffu, v, m);
    int w = threadIdx.x >> 5;
    if ((threadIdx.x & 31) == 0) red[w] = v;
    __syncthreads();
    if (threadIdx.x < 8) {
        float t = red[threadIdx.x];
        t += __shfl_xor_sync(0xffu, t, 4);
        t += __shfl_xor_sync(0xffu, t, 2);
        t += __shfl_xor_sync(0xffu, t, 1);
        if (threadIdx.x == 0) total = t;
    }
    __syncthreads();
    return total;
}

// ---------------- weight repack: W_{Q,K,V}[n,e,h] -> Wp[e, 3*768] ----------------
__global__ void pack_qkv_kernel(const float* __restrict__ WQ, const float* __restrict__ WK,
                                const float* __restrict__ WV, const float* __restrict__ bQ,
                                const float* __restrict__ bK, const float* __restrict__ bV,
                                float* __restrict__ Wp, float* __restrict__ bp) {
    int idx = blockIdx.x * blockDim.x + threadIdx.x;
    if (idx < D_MODEL * QKV_N) {
        int e = idx / QKV_N;
        int col = idx - e * QKV_N;
        int which = col / D_MODEL;
        int c = col - which * D_MODEL;     // n*64 + h
        int n = c >> 6;
        int hd = c & 63;
        const float* W = (which == 0) ? WQ : (which == 1) ? WK : WV;
        Wp[idx] = W[((size_t)n * D_MODEL + e) * D_HEAD + hd];
    }
    if (idx < QKV_N) {
        int which = idx / D_MODEL;
        int c = idx - which * D_MODEL;
        const float* bb = (which == 0) ? bQ : (which == 1) ? bK : bV;
        bp[idx] = bb[c];
    }
}

// ---------------- layernorm: one block per row (768 cols, 256 threads) ----------------
__global__ void ln_kernel(const float* __restrict__ x, const float* __restrict__ w,
                          const float* __restrict__ b, float* __restrict__ y) {
    int row = blockIdx.x;
    const float* xr = x + (size_t)row * D_MODEL;
    float* yr = y + (size_t)row * D_MODEL;
    int tid = threadIdx.x;
    float v0 = xr[tid], v1 = xr[tid + 256], v2 = xr[tid + 512];
    float s = block_sum256(v0 + v1 + v2);
    float mean = s * (1.0f / D_MODEL);
    float d0 = v0 - mean, d1 = v1 - mean, d2 = v2 - mean;
    float sq = block_sum256(d0 * d0 + d1 * d1 + d2 * d2);
    float rstd = rsqrtf(sq * (1.0f / D_MODEL) + 1e-5f);
    yr[tid]       = d0 * rstd * w[tid]       + b[tid];
    yr[tid + 256] = d1 * rstd * w[tid + 256] + b[tid + 256];
    yr[tid + 512] = d2 * rstd * w[tid + 512] + b[tid + 512];
}

// ---------------- generic SGEMM: C[M,N] = A[M,K] @ B[K,N] + bias (+gelu)(+res) ----------
// tile 128x64, BK=16, 256 threads, 8x4 per thread
template<int GELU, int RES>
__global__ void gemm_kernel(const float* __restrict__ A, const float* __restrict__ B,
                            const float* __restrict__ bias, const float* __restrict__ res,
                            float* __restrict__ C, int M, int N, int K) {
    __shared__ float As[16 * 132];
    __shared__ float Bs[16 * 68];
    const int bm = blockIdx.y * 128;
    const int bn = blockIdx.x * 64;
    const int tid = threadIdx.x;
    const int tx = tid & 15;   // col group
    const int ty = tid >> 4;   // row group

    float acc[8][4];
    #pragma unroll
    for (int i = 0; i < 8; i++)
        #pragma unroll
        for (int j = 0; j < 4; j++) acc[i][j] = 0.0f;

    for (int bk = 0; bk < K; bk += 16) {
        #pragma unroll
        for (int u = 0; u < 8; u++) {
            int idx = tid + u * 256;           // 0..2047
            int m = idx >> 4;
            int kk = idx & 15;
            As[kk * 132 + m] = A[(size_t)(bm + m) * K + bk + kk];
        }
        #pragma unroll
        for (int u = 0; u < 4; u++) {
            int idx = tid + u * 256;           // 0..1023
            int kk = idx >> 6;
            int c = idx & 63;
            Bs[kk * 68 + c] = B[(size_t)(bk + kk) * N + bn + c];
        }
        __syncthreads();
        #pragma unroll
        for (int kk = 0; kk < 16; kk++) {
            float4 a0 = *(const float4*)&As[kk * 132 + ty * 8];
            float4 a1 = *(const float4*)&As[kk * 132 + ty * 8 + 4];
            float4 b0 = *(const float4*)&Bs[kk * 68 + tx * 4];
            float a[8] = {a0.x, a0.y, a0.z, a0.w, a1.x, a1.y, a1.z, a1.w};
            float bb[4] = {b0.x, b0.y, b0.z, b0.w};
            #pragma unroll
            for (int i = 0; i < 8; i++)
                #pragma unroll
                for (int j = 0; j < 4; j++) acc[i][j] += a[i] * bb[j];
        }
        __syncthreads();
    }

    float4 bv = *(const float4*)&bias[bn + tx * 4];
    #pragma unroll
    for (int i = 0; i < 8; i++) {
        int row = bm + ty * 8 + i;
        float o0 = acc[i][0] + bv.x;
        float o1 = acc[i][1] + bv.y;
        float o2 = acc[i][2] + bv.z;
        float o3 = acc[i][3] + bv.w;
        if (GELU) { o0 = gelu_new_f(o0); o1 = gelu_new_f(o1); o2 = gelu_new_f(o2); o3 = gelu_new_f(o3); }
        if (RES) {
            float4 r = *(const float4*)&res[(size_t)row * N + bn + tx * 4];
            o0 += r.x; o1 += r.y; o2 += r.z; o3 += r.w;
        }
        float4 o = make_float4(o0, o1, o2, o3);
        *(float4*)&C[(size_t)row * N + bn + tx * 4] = o;
    }
}

// ---------------- fused causal attention (flash-style) -------------------------
// grid: (SEQ/64, BATCH*N_HEADS); block: 256 threads; 64q x 64k tiles, d=64
// qkv layout: [ROWS, 2304]; q at col h*64, k at 768+h*64, v at 1536+h*64
#define ATTN_SMEM ((64*64 + 64*68 + 64*64 + 64*68) * 4)

__global__ void attn_kernel(const float* __restrict__ qkv, float* __restrict__ z) {
    const int qt = blockIdx.x;               // query tile 0..31
    const int bh = blockIdx.y;               // 0..23
    const int b = bh / N_HEADS;
    const int h = bh - b * N_HEADS;

    extern __shared__ float sm[];
    float* q_s = sm;                  // [64][64]
    float* k_s = q_s + 64 * 64;       // [64][68]
    float* v_s = k_s + 64 * 68;       // [64][64]
    float* p_s = v_s + 64 * 64;       // [64][68]

    const int tid = threadIdx.x;
    const int tx = tid & 15;
    const int ty = tid >> 4;

    const size_t rowbase = (size_t)b * SEQ;
    const float* qbase = qkv + (rowbase) * QKV_N + h * 64;
    const float* kbase = qbase + D_MODEL;
    const float* vbase = qbase + 2 * D_MODEL;

    // load Q tile
    #pragma unroll
    for (int u = 0; u < 16; u++) {
        int idx = tid + u * 256;
        int r = idx >> 6, c = idx & 63;
        q_s[r * 64 + c] = qbase[(size_t)(qt * 64 + r) * QKV_N + c];
    }

    float m[4], l[4], acc[4][4];
    #pragma unroll
    for (int i = 0; i < 4; i++) {
        m[i] = -INFINITY; l[i] = 0.0f;
        #pragma unroll
        for (int j = 0; j < 4; j++) acc[i][j] = 0.0f;
    }

    for (int kt = 0; kt <= qt; kt++) {
        __syncthreads();   // prev PV done (also covers the initial Q load)
        #pragma unroll
        for (int u = 0; u < 16; u++) {
            int idx = tid + u * 256;
            int r = idx >> 6, c = idx & 63;
            size_t grow = (size_t)(kt * 64 + r) * QKV_N;
            k_s[r * 68 + c] = kbase[grow + c];
            v_s[r * 64 + c] = vbase[grow + c];
        }
        __syncthreads();

        // S = Q K^T (4x4 per thread)
        float s[4][4];
        #pragma unroll
        for (int i = 0; i < 4; i++)
            #pragma unroll
            for (int j = 0; j < 4; j++) s[i][j] = 0.0f;

        #pragma unroll
        for (int d = 0; d < 64; d += 4) {
            float4 a[4], kb[4];
            #pragma unroll
            for (int i = 0; i < 4; i++) a[i] = *(const float4*)&q_s[(ty * 4 + i) * 64 + d];
            #pragma unroll
            for (int j = 0; j < 4; j++) kb[j] = *(const float4*)&k_s[(tx * 4 + j) * 68 + d];
            #pragma unroll
            for (int i = 0; i < 4; i++)
                #pragma unroll
                for (int j = 0; j < 4; j++) {
                    s[i][j] += a[i].x * kb[j].x + a[i].y * kb[j].y
                             + a[i].z * kb[j].z + a[i].w * kb[j].w;
                }
        }

        // scale + causal mask + online softmax
        #pragma unroll
        for (int i = 0; i < 4; i++) {
            int qi = qt * 64 + ty * 4 + i;
            float tm = -INFINITY;
            #pragma unroll
            for (int j = 0; j < 4; j++) {
                int kj = kt * 64 + tx * 4 + j;
                s[i][j] = (kj <= qi) ? s[i][j] * 0.125f : IGNORE_V;
                tm = fmaxf(tm, s[i][j]);
            }
            tm = rowred_max16(tm);
            float newm = fmaxf(m[i], tm);
            float alpha = expf(m[i] - newm);
            float ts = 0.0f;
            #pragma unroll
            for (int j = 0; j < 4; j++) {
                float p = expf(s[i][j] - newm);
                ts += p;
                p_s[(ty * 4 + i) * 68 + tx * 4 + j] = p;
            }
            ts = rowred_sum16(ts);
            l[i] = l[i] * alpha + ts;
            m[i] = newm;
            #pragma unroll
            for (int j = 0; j < 4; j++) acc[i][j] *= alpha;
        }
        __syncthreads();

        // O += P @ V
        #pragma unroll
        for (int kk = 0; kk < 64; kk += 4) {
            float4 pr[4];
            #pragma unroll
            for (int i = 0; i < 4; i++) pr[i] = *(const float4*)&p_s[(ty * 4 + i) * 68 + kk];
            #pragma unroll
            for (int u = 0; u < 4; u++) {
                float4 vv = *(const float4*)&v_s[(kk + u) * 64 + tx * 4];
                #pragma unroll
                for (int i = 0; i < 4; i++) {
                    float p = (u == 0) ? pr[i].x : (u == 1) ? pr[i].y : (u == 2) ? pr[i].z : pr[i].w;
                    acc[i][0] += p * vv.x;
                    acc[i][1] += p * vv.y;
                    acc[i][2] += p * vv.z;
                    acc[i][3] += p * vv.w;
                }
            }
        }
    }

    // write z[b, q, h, :]
    #pragma unroll
    for (int i = 0; i < 4; i++) {
        int row = qt * 64 + ty * 4 + i;
        float inv = 1.0f / l[i];
        float4 o = make_float4(acc[i][0] * inv, acc[i][1] * inv, acc[i][2] * inv, acc[i][3] * inv);
        *(float4*)&z[(rowbase + row) * D_MODEL + h * 64 + tx * 4] = o;
    }
}

// ---------------- launch ----------------
extern "C" void kernel_launch(void* const* d_in, const int* in_sizes, int n_in,
                              void* d_out, int out_size) {
    const float* resid_pre = (const float*)d_in[0];
    const float* WQ   = (const float*)d_in[1];
    const float* bQ   = (const float*)d_in[2];
    const float* WK   = (const float*)d_in[3];
    const float* bK   = (const float*)d_in[4];
    const float* WV   = (const float*)d_in[5];
    const float* bV   = (const float*)d_in[6];
    const float* WO   = (const float*)d_in[7];
    const float* bO   = (const float*)d_in[8];
    const float* ln1w = (const float*)d_in[9];
    const float* ln1b = (const float*)d_in[10];
    const float* ln2w = (const float*)d_in[11];
    const float* ln2b = (const float*)d_in[12];
    const float* Win  = (const float*)d_in[13];
    const float* bin  = (const float*)d_in[14];
    const float* Wout = (const float*)d_in[15];
    const float* bout = (const float*)d_in[16];
    float* out = (float*)d_out;

    float *x1, *qkv, *z, *mid, *x2, *hidden, *wp, *bp;
    cudaGetSymbolAddress((void**)&x1,     g_x1);
    cudaGetSymbolAddress((void**)&qkv,    g_qkv);
    cudaGetSymbolAddress((void**)&z,      g_z);
    cudaGetSymbolAddress((void**)&mid,    g_mid);
    cudaGetSymbolAddress((void**)&x2,     g_x2);
    cudaGetSymbolAddress((void**)&hidden, g_hidden);
    cudaGetSymbolAddress((void**)&wp,     g_wqkv);
    cudaGetSymbolAddress((void**)&bp,     g_bqkv);

    cudaFuncSetAttribute(attn_kernel, cudaFuncAttributeMaxDynamicSharedMemorySize, ATTN_SMEM);

    // 1. repack QKV weights+bias into fused [768, 2304]
    pack_qkv_kernel<<<(D_MODEL * QKV_N + 255) / 256, 256>>>(WQ, WK, WV, bQ, bK, bV, wp, bp);
    // 2. LN1
    ln_kernel<<<ROWS, 256>>>(resid_pre, ln1w, ln1b, x1);
    // 3. fused QKV projection: [4096,768] @ [768,2304]
    gemm_kernel<0, 0><<<dim3(QKV_N / 64, ROWS / 128), 256>>>(x1, wp, bp, nullptr, qkv, ROWS, QKV_N, D_MODEL);
    // 4. causal attention -> z [4096, 768]
    attn_kernel<<<dim3(SEQ / 64, BATCH * N_HEADS), 256, ATTN_SMEM>>>(qkv, z);
    // 5. O projection + residual: mid = z @ W_O + b_O + resid_pre
    gemm_kernel<0, 1><<<dim3(D_MODEL / 64, ROWS / 128), 256>>>(z, WO, bO, resid_pre, mid, ROWS, D_MODEL, D_MODEL);
    // 6. LN2
    ln_kernel<<<ROWS, 256>>>(mid, ln2w, ln2b, x2);
    // 7. MLP up + gelu: hidden = gelu(x2 @ W_in + b_in)
    gemm_kernel<1, 0><<<dim3(D_MLP / 64, ROWS / 128), 256>>>(x2, Win, bin, nullptr, hidden, ROWS, D_MLP, D_MODEL);
    // 8. MLP down + residual: out = hidden @ W_out + b_out + mid
    gemm_kernel<0, 1><<<dim3(D_MODEL / 64, ROWS / 128), 256>>>(hidden, Wout, bout, mid, out, ROWS, D_MODEL, D_MLP);
}

// round 2
// speedup vs baseline: 1.6879x; 1.6879x over previous
#include <cuda_runtime.h>
#include <cuda_bf16.h>
#include <math.h>
#include <stdint.h>

// ---------------- problem constants ----------------
#define D_MODEL 768
#define N_HEADS 12
#define D_HEAD  64
#define D_MLP   3072
#define BATCH   2
#define SEQ     2048
#define ROWS    (BATCH*SEQ)          // 4096
#define QKV_N   (3*D_MODEL)          // 2304
#define IGNORE_V (-100000.0f)

// ---------------- device scratch (no runtime alloc allowed) ----------------
__device__ float g_x1    [ROWS * D_MODEL];
__device__ float g_qkv   [ROWS * QKV_N];
__device__ float g_z     [ROWS * D_MODEL];
__device__ float g_mid   [ROWS * D_MODEL];
__device__ float g_x2    [ROWS * D_MODEL];
__device__ float g_hidden[ROWS * D_MLP];
__device__ float g_wqkv  [D_MODEL * QKV_N];
__device__ float g_bqkv  [QKV_N];

// ---------------- helpers ----------------
__device__ __forceinline__ float fast_tanh(float x) {
    float y;
    asm("tanh.approx.f32 %0, %1;" : "=f"(y) : "f"(x));
    return y;
}

__device__ __forceinline__ float gelu_new_f(float x) {
    const float c = 0.7978845608028654f;
    float x3 = x * x * x;
    return 0.5f * x * (1.0f + fast_tanh(c * (x + 0.044715f * x3)));
}

__device__ __forceinline__ float tf32r(float x) {
    uint32_t u;
    asm("cvt.rna.tf32.f32 %0, %1;" : "=r"(u) : "f"(x));
    return __uint_as_float(u);
}

__device__ __forceinline__ void mma_tf32(float& c0, float& c1, float& c2, float& c3,
                                         uint32_t a0, uint32_t a1, uint32_t a2, uint32_t a3,
                                         uint32_t b0, uint32_t b1) {
    asm volatile(
        "mma.sync.aligned.m16n8k8.row.col.f32.tf32.tf32.f32 "
        "{%0,%1,%2,%3}, {%4,%5,%6,%7}, {%8,%9}, {%0,%1,%2,%3};\n"
        : "+f"(c0), "+f"(c1), "+f"(c2), "+f"(c3)
        : "r"(a0), "r"(a1), "r"(a2), "r"(a3), "r"(b0), "r"(b1));
}

__device__ __forceinline__ float rowred_max16(float v) {
    v = fmaxf(v, __shfl_xor_sync(0xffffffffu, v, 8));
    v = fmaxf(v, __shfl_xor_sync(0xffffffffu, v, 4));
    v = fmaxf(v, __shfl_xor_sync(0xffffffffu, v, 2));
    v = fmaxf(v, __shfl_xor_sync(0xffffffffu, v, 1));
    return v;
}
__device__ __forceinline__ float rowred_sum16(float v) {
    v += __shfl_xor_sync(0xffffffffu, v, 8);
    v += __shfl_xor_sync(0xffffffffu, v, 4);
    v += __shfl_xor_sync(0xffffffffu, v, 2);
    v += __shfl_xor_sync(0xffffffffu, v, 1);
    return v;
}

// block-wide sum for 256 threads
__device__ __forceinline__ float block_sum256(float v) {
    __shared__ float red[8];
    __shared__ float total;
    #pragma unroll
    for (int m = 16; m >= 1; m >>= 1) v += __shfl_xor_sync(0xffffffffu, v, m);
    int w = threadIdx.x >> 5;
    if ((threadIdx.x & 31) == 0) red[w] = v;
    __syncthreads();
    if (threadIdx.x < 8) {
        float t = red[threadIdx.x];
        t += __shfl_xor_sync(0xffu, t, 4);
        t += __shfl_xor_sync(0xffu, t, 2);
        t += __shfl_xor_sync(0xffu, t, 1);
        if (threadIdx.x == 0) total = t;
    }
    __syncthreads();
    return total;
}

// ---------------- weight repack: W_{Q,K,V}[n,e,h] -> Wp[e, 3*768] ----------------
__global__ void pack_qkv_kernel(const float* __restrict__ WQ, const float* __restrict__ WK,
                                const float* __restrict__ WV, const float* __restrict__ bQ,
                                const float* __restrict__ bK, const float* __restrict__ bV,
                                float* __restrict__ Wp, float* __restrict__ bp) {
    int idx = blockIdx.x * blockDim.x + threadIdx.x;
    if (idx < D_MODEL * QKV_N) {
        int e = idx / QKV_N;
        int col = idx - e * QKV_N;
        int which = col / D_MODEL;
        int c = col - which * D_MODEL;     // n*64 + h
        int n = c >> 6;
        int hd = c & 63;
        const float* W = (which == 0) ? WQ : (which == 1) ? WK : WV;
        Wp[idx] = W[((size_t)n * D_MODEL + e) * D_HEAD + hd];
    }
    if (idx < QKV_N) {
        int which = idx / D_MODEL;
        int c = idx - which * D_MODEL;
        const float* bb = (which == 0) ? bQ : (which == 1) ? bK : bV;
        bp[idx] = bb[c];
    }
}

// ---------------- layernorm: one block per row (768 cols, 256 threads) ----------------
__global__ void ln_kernel(const float* __restrict__ x, const float* __restrict__ w,
                          const float* __restrict__ b, float* __restrict__ y) {
    int row = blockIdx.x;
    const float* xr = x + (size_t)row * D_MODEL;
    float* yr = y + (size_t)row * D_MODEL;
    int tid = threadIdx.x;
    float v0 = xr[tid], v1 = xr[tid + 256], v2 = xr[tid + 512];
    float s = block_sum256(v0 + v1 + v2);
    float mean = s * (1.0f / D_MODEL);
    float d0 = v0 - mean, d1 = v1 - mean, d2 = v2 - mean;
    float sq = block_sum256(d0 * d0 + d1 * d1 + d2 * d2);
    float rstd = rsqrtf(sq * (1.0f / D_MODEL) + 1e-5f);
    yr[tid]       = d0 * rstd * w[tid]       + b[tid];
    yr[tid + 256] = d1 * rstd * w[tid + 256] + b[tid + 256];
    yr[tid + 512] = d2 * rstd * w[tid + 512] + b[tid + 512];
}

// ---------------- tf32 tensor-core GEMM -----------------------------------------
// C[M,N] = A[M,K] @ B[K,N] + bias (+gelu)(+res)
// BM=128, BK=32, BN template (128 or 64). 256 threads, 8 warps (2m x 4n),
// warp tile 64 x BN/4, mma m16n8k8 tf32. Double-buffered smem.
template<int BN, int GELU, int RES>
__global__ __launch_bounds__(256) void mma_gemm(
        const float* __restrict__ A, const float* __restrict__ B,
        const float* __restrict__ bias, const float* __restrict__ res,
        float* __restrict__ C, int M, int N, int K) {
    constexpr int LDA = 36;          // A smem: [128 m][36]  (k padded 32->36)
    constexpr int LDB = BN + 8;      // B smem: [32 k][BN+8]
    constexpr int A_STAGE = 128 * LDA;
    constexpr int B_STAGE = 32 * LDB;
    constexpr int NT = BN / 32;      // n8-tiles per warp
    constexpr int TPR = BN / 4;      // threads per B k-row (float4 granules)
    constexpr int BITER = TPR / 8;   // B global-load iterations
    constexpr int KSTRIDE = 256 / TPR;

    extern __shared__ float smem[];
    float* Asm = smem;
    float* Bsm = smem + 2 * A_STAGE;

    const int tid = threadIdx.x;
    const int lane = tid & 31;
    const int wid = tid >> 5;
    const int lr = lane >> 2;        // 0..7
    const int lc = lane & 3;         // 0..3
    const int warp_m = wid & 1;
    const int warp_n = wid >> 1;
    const int bm = blockIdx.y * 128;
    const int bn = blockIdx.x * BN;

    const int am0 = tid >> 3;        // 0..31 (A row group)
    const int akq = (tid & 7) * 4;   // 0..28 (A k quad)
    const int bk0 = tid / TPR;
    const int bn0 = (tid % TPR) * 4;

    float4 aR[4];
    float4 bR[BITER];
    float acc[4][NT][4];
    #pragma unroll
    for (int i = 0; i < 4; i++)
        #pragma unroll
        for (int j = 0; j < NT; j++)
            #pragma unroll
            for (int u = 0; u < 4; u++) acc[i][j][u] = 0.0f;

    const int ntiles = K / 32;

    // prologue: load tile 0
    #pragma unroll
    for (int i = 0; i < 4; i++)
        aR[i] = *(const float4*)(A + (size_t)(bm + am0 + 32 * i) * K + akq);
    #pragma unroll
    for (int i = 0; i < BITER; i++)
        bR[i] = *(const float4*)(B + (size_t)(bk0 + KSTRIDE * i) * N + bn + bn0);
    {
        float* As_ = Asm;
        float* Bs_ = Bsm;
        #pragma unroll
        for (int i = 0; i < 4; i++) {
            float4 v = aR[i];
            v.x = tf32r(v.x); v.y = tf32r(v.y); v.z = tf32r(v.z); v.w = tf32r(v.w);
            *(float4*)(As_ + (am0 + 32 * i) * LDA + akq) = v;
        }
        #pragma unroll
        for (int i = 0; i < BITER; i++) {
            float4 v = bR[i];
            v.x = tf32r(v.x); v.y = tf32r(v.y); v.z = tf32r(v.z); v.w = tf32r(v.w);
            *(float4*)(Bs_ + (bk0 + KSTRIDE * i) * LDB + bn0) = v;
        }
    }
    __syncthreads();

    for (int t = 0; t < ntiles; t++) {
        const int bk_next = (t + 1) * 32;
        if (t + 1 < ntiles) {
            #pragma unroll
            for (int i = 0; i < 4; i++)
                aR[i] = *(const float4*)(A + (size_t)(bm + am0 + 32 * i) * K + bk_next + akq);
            #pragma unroll
            for (int i = 0; i < BITER; i++)
                bR[i] = *(const float4*)(B + (size_t)(bk_next + bk0 + KSTRIDE * i) * N + bn + bn0);
        }

        // compute on buffer t&1
        {
            const uint32_t* As_ = (const uint32_t*)(Asm + (t & 1) * A_STAGE);
            const uint32_t* Bs_ = (const uint32_t*)(Bsm + (t & 1) * B_STAGE);
            #pragma unroll
            for (int kk = 0; kk < 4; kk++) {
                uint32_t a[4][4];
                uint32_t b[NT][2];
                #pragma unroll
                for (int i = 0; i < 4; i++) {
                    int r = warp_m * 64 + i * 16 + lr;
                    int c = kk * 8 + lc;
                    a[i][0] = As_[r * LDA + c];
                    a[i][1] = As_[(r + 8) * LDA + c];
                    a[i][2] = As_[r * LDA + c + 4];
                    a[i][3] = As_[(r + 8) * LDA + c + 4];
                }
                #pragma unroll
                for (int j = 0; j < NT; j++) {
                    int cc = warp_n * TPR + j * 8 + lr;
                    b[j][0] = Bs_[(kk * 8 + lc) * LDB + cc];
                    b[j][1] = Bs_[(kk * 8 + lc + 4) * LDB + cc];
                }
                #pragma unroll
                for (int i = 0; i < 4; i++)
                    #pragma unroll
                    for (int j = 0; j < NT; j++)
                        mma_tf32(acc[i][j][0], acc[i][j][1], acc[i][j][2], acc[i][j][3],
                                 a[i][0], a[i][1], a[i][2], a[i][3], b[j][0], b[j][1]);
            }
        }

        if (t + 1 < ntiles) {
            float* As_ = Asm + ((t + 1) & 1) * A_STAGE;
            float* Bs_ = Bsm + ((t + 1) & 1) * B_STAGE;
            #pragma unroll
            for (int i = 0; i < 4; i++) {
                float4 v = aR[i];
                v.x = tf32r(v.x); v.y = tf32r(v.y); v.z = tf32r(v.z); v.w = tf32r(v.w);
                *(float4*)(As_ + (am0 + 32 * i) * LDA + akq) = v;
            }
            #pragma unroll
            for (int i = 0; i < BITER; i++) {
                float4 v = bR[i];
                v.x = tf32r(v.x); v.y = tf32r(v.y); v.z = tf32r(v.z); v.w = tf32r(v.w);
                *(float4*)(Bs_ + (bk0 + KSTRIDE * i) * LDB + bn0) = v;
            }
        }
        __syncthreads();
    }

    // epilogue
    #pragma unroll
    for (int i = 0; i < 4; i++) {
        #pragma unroll
        for (int j = 0; j < NT; j++) {
            int r0 = bm + warp_m * 64 + i * 16 + lr;
            int cc = bn + warp_n * TPR + j * 8 + lc * 2;
            float2 bv = *(const float2*)&bias[cc];
            // row r0: acc[0], acc[1]
            {
                float o0 = acc[i][j][0] + bv.x;
                float o1 = acc[i][j][1] + bv.y;
                if (GELU) { o0 = gelu_new_f(o0); o1 = gelu_new_f(o1); }
                if (RES) {
                    float2 rv = *(const float2*)&res[(size_t)r0 * N + cc];
                    o0 += rv.x; o1 += rv.y;
                }
                *(float2*)&C[(size_t)r0 * N + cc] = make_float2(o0, o1);
            }
            // row r0+8: acc[2], acc[3]
            {
                int r1 = r0 + 8;
                float o0 = acc[i][j][2] + bv.x;
                float o1 = acc[i][j][3] + bv.y;
                if (GELU) { o0 = gelu_new_f(o0); o1 = gelu_new_f(o1); }
                if (RES) {
                    float2 rv = *(const float2*)&res[(size_t)r1 * N + cc];
                    o0 += rv.x; o1 += rv.y;
                }
                *(float2*)&C[(size_t)r1 * N + cc] = make_float2(o0, o1);
            }
        }
    }
}

// ---------------- fused causal attention (flash-style) -------------------------
// grid: (SEQ/64, BATCH*N_HEADS); block: 256 threads; 64q x 64k tiles, d=64
#define ATTN_SMEM ((64*64 + 64*68 + 64*64 + 64*68) * 4)

__global__ __launch_bounds__(256) void attn_kernel(const float* __restrict__ qkv, float* __restrict__ z) {
    const int qt = blockIdx.x;               // query tile 0..31
    const int bh = blockIdx.y;               // 0..23
    const int b = bh / N_HEADS;
    const int h = bh - b * N_HEADS;

    extern __shared__ float sm[];
    float* q_s = sm;                  // [64][64]
    float* k_s = q_s + 64 * 64;       // [64][68]
    float* v_s = k_s + 64 * 68;       // [64][64]
    float* p_s = v_s + 64 * 64;       // [64][68]

    const int tid = threadIdx.x;
    const int tx = tid & 15;
    const int ty = tid >> 4;

    const size_t rowbase = (size_t)b * SEQ;
    const float* qbase = qkv + (rowbase) * QKV_N + h * 64;
    const float* kbase = qbase + D_MODEL;
    const float* vbase = qbase + 2 * D_MODEL;

    // load Q tile
    #pragma unroll
    for (int u = 0; u < 16; u++) {
        int idx = tid + u * 256;
        int r = idx >> 6, c = idx & 63;
        q_s[r * 64 + c] = qbase[(size_t)(qt * 64 + r) * QKV_N + c];
    }

    float m[4], l[4], acc[4][4];
    #pragma unroll
    for (int i = 0; i < 4; i++) {
        m[i] = -INFINITY; l[i] = 0.0f;
        #pragma unroll
        for (int j = 0; j < 4; j++) acc[i][j] = 0.0f;
    }

    for (int kt = 0; kt <= qt; kt++) {
        __syncthreads();   // prev PV done (also covers the initial Q load)
        #pragma unroll
        for (int u = 0; u < 16; u++) {
            int idx = tid + u * 256;
            int r = idx >> 6, c = idx & 63;
            size_t grow = (size_t)(kt * 64 + r) * QKV_N;
            k_s[r * 68 + c] = kbase[grow + c];
            v_s[r * 64 + c] = vbase[grow + c];
        }
        __syncthreads();

        // S = Q K^T (4x4 per thread)
        float s[4][4];
        #pragma unroll
        for (int i = 0; i < 4; i++)
            #pragma unroll
            for (int j = 0; j < 4; j++) s[i][j] = 0.0f;

        #pragma unroll
        for (int d = 0; d < 64; d += 4) {
            float4 a[4], kb[4];
            #pragma unroll
            for (int i = 0; i < 4; i++) a[i] = *(const float4*)&q_s[(ty * 4 + i) * 64 + d];
            #pragma unroll
            for (int j = 0; j < 4; j++) kb[j] = *(const float4*)&k_s[(tx * 4 + j) * 68 + d];
            #pragma unroll
            for (int i = 0; i < 4; i++)
                #pragma unroll
                for (int j = 0; j < 4; j++) {
                    s[i][j] += a[i].x * kb[j].x + a[i].y * kb[j].y
                             + a[i].z * kb[j].z + a[i].w * kb[j].w;
                }
        }

        // scale + causal mask + online softmax
        #pragma unroll
        for (int i = 0; i < 4; i++) {
            int qi = qt * 64 + ty * 4 + i;
            float tm = -INFINITY;
            #pragma unroll
            for (int j = 0; j < 4; j++) {
                int kj = kt * 64 + tx * 4 + j;
                s[i][j] = (kj <= qi) ? s[i][j] * 0.125f : IGNORE_V;
                tm = fmaxf(tm, s[i][j]);
            }
            tm = rowred_max16(tm);
            float newm = fmaxf(m[i], tm);
            float alpha = __expf(m[i] - newm);
            float ts = 0.0f;
            #pragma unroll
            for (int j = 0; j < 4; j++) {
                float p = __expf(s[i][j] - newm);
                ts += p;
                p_s[(ty * 4 + i) * 68 + tx * 4 + j] = p;
            }
            ts = rowred_sum16(ts);
            l[i] = l[i] * alpha + ts;
            m[i] = newm;
            #pragma unroll
            for (int j = 0; j < 4; j++) acc[i][j] *= alpha;
        }
        __syncthreads();

        // O += P @ V
        #pragma unroll
        for (int kk = 0; kk < 64; kk += 4) {
            float4 pr[4];
            #pragma unroll
            for (int i = 0; i < 4; i++) pr[i] = *(const float4*)&p_s[(ty * 4 + i) * 68 + kk];
            #pragma unroll
            for (int u = 0; u < 4; u++) {
                float4 vv = *(const float4*)&v_s[(kk + u) * 64 + tx * 4];
                #pragma unroll
                for (int i = 0; i < 4; i++) {
                    float p = (u == 0) ? pr[i].x : (u == 1) ? pr[i].y : (u == 2) ? pr[i].z : pr[i].w;
                    acc[i][0] += p * vv.x;
                    acc[i][1] += p * vv.y;
                    acc[i][2] += p * vv.z;
                    acc[i][3] += p * vv.w;
                }
            }
        }
    }

    // write z[b, q, h, :]
    #pragma unroll
    for (int i = 0; i < 4; i++) {
        int row = qt * 64 + ty * 4 + i;
        float inv = 1.0f / l[i];
        float4 o = make_float4(acc[i][0] * inv, acc[i][1] * inv, acc[i][2] * inv, acc[i][3] * inv);
        *(float4*)&z[(rowbase + row) * D_MODEL + h * 64 + tx * 4] = o;
    }
}

// ---------------- launch ----------------
extern "C" void kernel_launch(void* const* d_in, const int* in_sizes, int n_in,
                              void* d_out, int out_size) {
    const float* resid_pre = (const float*)d_in[0];
    const float* WQ   = (const float*)d_in[1];
    const float* bQ   = (const float*)d_in[2];
    const float* WK   = (const float*)d_in[3];
    const float* bK   = (const float*)d_in[4];
    const float* WV   = (const float*)d_in[5];
    const float* bV   = (const float*)d_in[6];
    const float* WO   = (const float*)d_in[7];
    const float* bO   = (const float*)d_in[8];
    const float* ln1w = (const float*)d_in[9];
    const float* ln1b = (const float*)d_in[10];
    const float* ln2w = (const float*)d_in[11];
    const float* ln2b = (const float*)d_in[12];
    const float* Win  = (const float*)d_in[13];
    const float* bin  = (const float*)d_in[14];
    const float* Wout = (const float*)d_in[15];
    const float* bout = (const float*)d_in[16];
    float* out = (float*)d_out;

    float *x1, *qkv, *z, *mid, *x2, *hidden, *wp, *bp;
    cudaGetSymbolAddress((void**)&x1,     g_x1);
    cudaGetSymbolAddress((void**)&qkv,    g_qkv);
    cudaGetSymbolAddress((void**)&z,      g_z);
    cudaGetSymbolAddress((void**)&mid,    g_mid);
    cudaGetSymbolAddress((void**)&x2,     g_x2);
    cudaGetSymbolAddress((void**)&hidden, g_hidden);
    cudaGetSymbolAddress((void**)&wp,     g_wqkv);
    cudaGetSymbolAddress((void**)&bp,     g_bqkv);

    const int SMEM_BN128 = (2 * 128 * 36 + 2 * 32 * 136) * 4;   // 71680
    const int SMEM_BN64  = (2 * 128 * 36 + 2 * 32 * 72)  * 4;   // 55296

    cudaFuncSetAttribute(attn_kernel, cudaFuncAttributeMaxDynamicSharedMemorySize, ATTN_SMEM);
    cudaFuncSetAttribute(mma_gemm<128,0,0>, cudaFuncAttributeMaxDynamicSharedMemorySize, SMEM_BN128);
    cudaFuncSetAttribute(mma_gemm<128,1,0>, cudaFuncAttributeMaxDynamicSharedMemorySize, SMEM_BN128);
    cudaFuncSetAttribute(mma_gemm<64,0,1>,  cudaFuncAttributeMaxDynamicSharedMemorySize, SMEM_BN64);

    // 1. repack QKV weights+bias into fused [768, 2304]
    pack_qkv_kernel<<<(D_MODEL * QKV_N + 255) / 256, 256>>>(WQ, WK, WV, bQ, bK, bV, wp, bp);
    // 2. LN1
    ln_kernel<<<ROWS, 256>>>(resid_pre, ln1w, ln1b, x1);
    // 3. fused QKV projection: [4096,768] @ [768,2304]
    mma_gemm<128,0,0><<<dim3(QKV_N / 128, ROWS / 128), 256, SMEM_BN128>>>(
        x1, wp, bp, nullptr, qkv, ROWS, QKV_N, D_MODEL);
    // 4. causal attention -> z [4096, 768]
    attn_kernel<<<dim3(SEQ / 64, BATCH * N_HEADS), 256, ATTN_SMEM>>>(qkv, z);
    // 5. O projection + residual: mid = z @ W_O + b_O + resid_pre
    mma_gemm<64,0,1><<<dim3(D_MODEL / 64, ROWS / 128), 256, SMEM_BN64>>>(
        z, WO, bO, resid_pre, mid, ROWS, D_MODEL, D_MODEL);
    // 6. LN2
    ln_kernel<<<ROWS, 256>>>(mid, ln2w, ln2b, x2);
    // 7. MLP up + gelu: hidden = gelu(x2 @ W_in + b_in)
    mma_gemm<128,1,0><<<dim3(D_MLP / 128, ROWS / 128), 256, SMEM_BN128>>>(
        x2, Win, bin, nullptr, hidden, ROWS, D_MLP, D_MODEL);
    // 8. MLP down + residual: out = hidden @ W_out + b_out + mid
    mma_gemm<64,0,1><<<dim3(D_MODEL / 64, ROWS / 128), 256, SMEM_BN64>>>(
        hidden, Wout, bout, mid, out, ROWS, D_MODEL, D_MLP);
}

// round 3
// speedup vs baseline: 2.9954x; 1.7746x over previous
#include <cuda_runtime.h>
#include <cuda_bf16.h>
#include <math.h>
#include <stdint.h>

// ---------------- problem constants ----------------
#define D_MODEL 768
#define N_HEADS 12
#define D_HEAD  64
#define D_MLP   3072
#define BATCH   2
#define SEQ     2048
#define ROWS    (BATCH*SEQ)          // 4096
#define QKV_N   (3*D_MODEL)          // 2304

// ---------------- device scratch (no runtime alloc allowed) ----------------
__device__ float g_x1    [ROWS * D_MODEL];
__device__ float g_qkv   [ROWS * QKV_N];
__device__ float g_z     [ROWS * D_MODEL];
__device__ float g_mid   [ROWS * D_MODEL];
__device__ float g_x2    [ROWS * D_MODEL];
__device__ float g_hidden[ROWS * D_MLP];
__device__ float g_wqkv  [D_MODEL * QKV_N];
__device__ float g_bqkv  [QKV_N];

// ---------------- helpers ----------------
__device__ __forceinline__ float fast_tanh(float x) {
    float y;
    asm("tanh.approx.f32 %0, %1;" : "=f"(y) : "f"(x));
    return y;
}

__device__ __forceinline__ float gelu_new_f(float x) {
    const float c = 0.7978845608028654f;
    float x3 = x * x * x;
    return 0.5f * x * (1.0f + fast_tanh(c * (x + 0.044715f * x3)));
}

__device__ __forceinline__ float tf32r(float x) {
    uint32_t u;
    asm("cvt.rna.tf32.f32 %0, %1;" : "=r"(u) : "f"(x));
    return __uint_as_float(u);
}
__device__ __forceinline__ uint32_t tf32b(float x) {
    uint32_t u;
    asm("cvt.rna.tf32.f32 %0, %1;" : "=r"(u) : "f"(x));
    return u;
}

__device__ __forceinline__ void mma_tf32(float& c0, float& c1, float& c2, float& c3,
                                         uint32_t a0, uint32_t a1, uint32_t a2, uint32_t a3,
                                         uint32_t b0, uint32_t b1) {
    asm volatile(
        "mma.sync.aligned.m16n8k8.row.col.f32.tf32.tf32.f32 "
        "{%0,%1,%2,%3}, {%4,%5,%6,%7}, {%8,%9}, {%0,%1,%2,%3};\n"
        : "+f"(c0), "+f"(c1), "+f"(c2), "+f"(c3)
        : "r"(a0), "r"(a1), "r"(a2), "r"(a3), "r"(b0), "r"(b1));
}

// block-wide sum for 256 threads
__device__ __forceinline__ float block_sum256(float v) {
    __shared__ float red[8];
    __shared__ float total;
    #pragma unroll
    for (int m = 16; m >= 1; m >>= 1) v += __shfl_xor_sync(0xffffffffu, v, m);
    int w = threadIdx.x >> 5;
    if ((threadIdx.x & 31) == 0) red[w] = v;
    __syncthreads();
    if (threadIdx.x < 8) {
        float t = red[threadIdx.x];
        t += __shfl_xor_sync(0xffu, t, 4);
        t += __shfl_xor_sync(0xffu, t, 2);
        t += __shfl_xor_sync(0xffu, t, 1);
        if (threadIdx.x == 0) total = t;
    }
    __syncthreads();
    return total;
}

// ---------------- weight repack: W_{Q,K,V}[n,e,h] -> Wp[e, 3*768] ----------------
__global__ void pack_qkv_kernel(const float* __restrict__ WQ, const float* __restrict__ WK,
                                const float* __restrict__ WV, const float* __restrict__ bQ,
                                const float* __restrict__ bK, const float* __restrict__ bV,
                                float* __restrict__ Wp, float* __restrict__ bp) {
    int idx = blockIdx.x * blockDim.x + threadIdx.x;
    if (idx < D_MODEL * QKV_N) {
        int e = idx / QKV_N;
        int col = idx - e * QKV_N;
        int which = col / D_MODEL;
        int c = col - which * D_MODEL;     // n*64 + h
        int n = c >> 6;
        int hd = c & 63;
        const float* W = (which == 0) ? WQ : (which == 1) ? WK : WV;
        Wp[idx] = W[((size_t)n * D_MODEL + e) * D_HEAD + hd];
    }
    if (idx < QKV_N) {
        int which = idx / D_MODEL;
        int c = idx - which * D_MODEL;
        const float* bb = (which == 0) ? bQ : (which == 1) ? bK : bV;
        bp[idx] = bb[c];
    }
}

// ---------------- layernorm: one block per row (768 cols, 256 threads) ----------------
__global__ void ln_kernel(const float* __restrict__ x, const float* __restrict__ w,
                          const float* __restrict__ b, float* __restrict__ y) {
    int row = blockIdx.x;
    const float* xr = x + (size_t)row * D_MODEL;
    float* yr = y + (size_t)row * D_MODEL;
    int tid = threadIdx.x;
    float v0 = xr[tid], v1 = xr[tid + 256], v2 = xr[tid + 512];
    float s = block_sum256(v0 + v1 + v2);
    float mean = s * (1.0f / D_MODEL);
    float d0 = v0 - mean, d1 = v1 - mean, d2 = v2 - mean;
    float sq = block_sum256(d0 * d0 + d1 * d1 + d2 * d2);
    float rstd = rsqrtf(sq * (1.0f / D_MODEL) + 1e-5f);
    yr[tid]       = d0 * rstd * w[tid]       + b[tid];
    yr[tid + 256] = d1 * rstd * w[tid + 256] + b[tid + 256];
    yr[tid + 512] = d2 * rstd * w[tid + 512] + b[tid + 512];
}

// ---------------- tf32 tensor-core GEMM -----------------------------------------
template<int BN, int GELU, int RES>
__global__ __launch_bounds__(256) void mma_gemm(
        const float* __restrict__ A, const float* __restrict__ B,
        const float* __restrict__ bias, const float* __restrict__ res,
        float* __restrict__ C, int M, int N, int K) {
    constexpr int LDA = 36;
    constexpr int LDB = BN + 8;
    constexpr int A_STAGE = 128 * LDA;
    constexpr int B_STAGE = 32 * LDB;
    constexpr int NT = BN / 32;
    constexpr int TPR = BN / 4;
    constexpr int BITER = TPR / 8;
    constexpr int KSTRIDE = 256 / TPR;

    extern __shared__ float smem[];
    float* Asm = smem;
    float* Bsm = smem + 2 * A_STAGE;

    const int tid = threadIdx.x;
    const int lane = tid & 31;
    const int wid = tid >> 5;
    const int lr = lane >> 2;
    const int lc = lane & 3;
    const int warp_m = wid & 1;
    const int warp_n = wid >> 1;
    const int bm = blockIdx.y * 128;
    const int bn = blockIdx.x * BN;

    const int am0 = tid >> 3;
    const int akq = (tid & 7) * 4;
    const int bk0 = tid / TPR;
    const int bn0 = (tid % TPR) * 4;

    float4 aR[4];
    float4 bR[BITER];
    float acc[4][NT][4];
    #pragma unroll
    for (int i = 0; i < 4; i++)
        #pragma unroll
        for (int j = 0; j < NT; j++)
            #pragma unroll
            for (int u = 0; u < 4; u++) acc[i][j][u] = 0.0f;

    const int ntiles = K / 32;

    #pragma unroll
    for (int i = 0; i < 4; i++)
        aR[i] = *(const float4*)(A + (size_t)(bm + am0 + 32 * i) * K + akq);
    #pragma unroll
    for (int i = 0; i < BITER; i++)
        bR[i] = *(const float4*)(B + (size_t)(bk0 + KSTRIDE * i) * N + bn + bn0);
    {
        float* As_ = Asm;
        float* Bs_ = Bsm;
        #pragma unroll
        for (int i = 0; i < 4; i++) {
            float4 v = aR[i];
            v.x = tf32r(v.x); v.y = tf32r(v.y); v.z = tf32r(v.z); v.w = tf32r(v.w);
            *(float4*)(As_ + (am0 + 32 * i) * LDA + akq) = v;
        }
        #pragma unroll
        for (int i = 0; i < BITER; i++) {
            float4 v = bR[i];
            v.x = tf32r(v.x); v.y = tf32r(v.y); v.z = tf32r(v.z); v.w = tf32r(v.w);
            *(float4*)(Bs_ + (bk0 + KSTRIDE * i) * LDB + bn0) = v;
        }
    }
    __syncthreads();

    for (int t = 0; t < ntiles; t++) {
        const int bk_next = (t + 1) * 32;
        if (t + 1 < ntiles) {
            #pragma unroll
            for (int i = 0; i < 4; i++)
                aR[i] = *(const float4*)(A + (size_t)(bm + am0 + 32 * i) * K + bk_next + akq);
            #pragma unroll
            for (int i = 0; i < BITER; i++)
                bR[i] = *(const float4*)(B + (size_t)(bk_next + bk0 + KSTRIDE * i) * N + bn + bn0);
        }

        {
            const uint32_t* As_ = (const uint32_t*)(Asm + (t & 1) * A_STAGE);
            const uint32_t* Bs_ = (const uint32_t*)(Bsm + (t & 1) * B_STAGE);
            #pragma unroll
            for (int kk = 0; kk < 4; kk++) {
                uint32_t a[4][4];
                uint32_t b[NT][2];
                #pragma unroll
                for (int i = 0; i < 4; i++) {
                    int r = warp_m * 64 + i * 16 + lr;
                    int c = kk * 8 + lc;
                    a[i][0] = As_[r * LDA + c];
                    a[i][1] = As_[(r + 8) * LDA + c];
                    a[i][2] = As_[r * LDA + c + 4];
                    a[i][3] = As_[(r + 8) * LDA + c + 4];
                }
                #pragma unroll
                for (int j = 0; j < NT; j++) {
                    int cc = warp_n * TPR + j * 8 + lr;
                    b[j][0] = Bs_[(kk * 8 + lc) * LDB + cc];
                    b[j][1] = Bs_[(kk * 8 + lc + 4) * LDB + cc];
                }
                #pragma unroll
                for (int i = 0; i < 4; i++)
                    #pragma unroll
                    for (int j = 0; j < NT; j++)
                        mma_tf32(acc[i][j][0], acc[i][j][1], acc[i][j][2], acc[i][j][3],
                                 a[i][0], a[i][1], a[i][2], a[i][3], b[j][0], b[j][1]);
            }
        }

        if (t + 1 < ntiles) {
            float* As_ = Asm + ((t + 1) & 1) * A_STAGE;
            float* Bs_ = Bsm + ((t + 1) & 1) * B_STAGE;
            #pragma unroll
            for (int i = 0; i < 4; i++) {
                float4 v = aR[i];
                v.x = tf32r(v.x); v.y = tf32r(v.y); v.z = tf32r(v.z); v.w = tf32r(v.w);
                *(float4*)(As_ + (am0 + 32 * i) * LDA + akq) = v;
            }
            #pragma unroll
            for (int i = 0; i < BITER; i++) {
                float4 v = bR[i];
                v.x = tf32r(v.x); v.y = tf32r(v.y); v.z = tf32r(v.z); v.w = tf32r(v.w);
                *(float4*)(Bs_ + (bk0 + KSTRIDE * i) * LDB + bn0) = v;
            }
        }
        __syncthreads();
    }

    #pragma unroll
    for (int i = 0; i < 4; i++) {
        #pragma unroll
        for (int j = 0; j < NT; j++) {
            int r0 = bm + warp_m * 64 + i * 16 + lr;
            int cc = bn + warp_n * TPR + j * 8 + lc * 2;
            float2 bv = *(const float2*)&bias[cc];
            {
                float o0 = acc[i][j][0] + bv.x;
                float o1 = acc[i][j][1] + bv.y;
                if (GELU) { o0 = gelu_new_f(o0); o1 = gelu_new_f(o1); }
                if (RES) {
                    float2 rv = *(const float2*)&res[(size_t)r0 * N + cc];
                    o0 += rv.x; o1 += rv.y;
                }
                *(float2*)&C[(size_t)r0 * N + cc] = make_float2(o0, o1);
            }
            {
                int r1 = r0 + 8;
                float o0 = acc[i][j][2] + bv.x;
                float o1 = acc[i][j][3] + bv.y;
                if (GELU) { o0 = gelu_new_f(o0); o1 = gelu_new_f(o1); }
                if (RES) {
                    float2 rv = *(const float2*)&res[(size_t)r1 * N + cc];
                    o0 += rv.x; o1 += rv.y;
                }
                *(float2*)&C[(size_t)r1 * N + cc] = make_float2(o0, o1);
            }
        }
    }
}

// ---------------- tf32 MMA flash attention --------------------------------------
// grid: (SEQ/128, BATCH*N_HEADS); 256 threads = 8 warps, each warp 16 q-rows.
// smem: k_s[64][68], v_s[64][72], p_s[128][68] (p_s doubles as Q staging)
#define LDK 68
#define LDV 72
#define LDP 68
#define ATTN_SMEM ((64*LDK + 64*LDV + 128*LDP) * 4)

__global__ __launch_bounds__(256) void attn_mma_kernel(const float* __restrict__ qkv,
                                                       float* __restrict__ z) {
    const int qt = (SEQ / 128 - 1) - blockIdx.x;     // heaviest tiles first
    const int bh = blockIdx.y;
    const int b = bh / N_HEADS;
    const int h = bh - b * N_HEADS;

    extern __shared__ float sm[];
    float* k_s = sm;                   // [64][LDK]
    float* v_s = sm + 64 * LDK;        // [64][LDV]
    float* p_s = sm + 64 * LDK + 64 * LDV;   // [128][LDP]

    const int tid = threadIdx.x;
    const int lane = tid & 31;
    const int wid = tid >> 5;
    const int lr = lane >> 2;      // 0..7
    const int lc = lane & 3;       // 0..3

    const size_t rowbase = (size_t)b * SEQ;
    const float* qb = qkv + rowbase * QKV_N + h * 64;
    const float* kb = qb + D_MODEL;
    const float* vb = qb + 2 * D_MODEL;

    // ---- stage Q (pre-scaled by 1/8) into p_s, then into register A-fragments ----
    #pragma unroll
    for (int i = 0; i < 8; i++) {
        int idx = tid + i * 256;           // 2048 float4 slots = 128 rows x 16
        int r = idx >> 4, c = (idx & 15) * 4;
        float4 v = *(const float4*)(qb + (size_t)(qt * 128 + r) * QKV_N + c);
        v.x *= 0.125f; v.y *= 0.125f; v.z *= 0.125f; v.w *= 0.125f;
        *(float4*)(p_s + r * LDP + c) = v;
    }
    __syncthreads();

    uint32_t qf[8][4];
    {
        int r0 = wid * 16 + lr;
        #pragma unroll
        for (int kk = 0; kk < 8; kk++) {
            int c = kk * 8 + lc;
            qf[kk][0] = tf32b(p_s[r0 * LDP + c]);
            qf[kk][1] = tf32b(p_s[(r0 + 8) * LDP + c]);
            qf[kk][2] = tf32b(p_s[r0 * LDP + c + 4]);
            qf[kk][3] = tf32b(p_s[(r0 + 8) * LDP + c + 4]);
        }
    }
    __syncwarp();

    const int row0 = qt * 128 + wid * 16 + lr;
    const int row1 = row0 + 8;

    float m0 = -INFINITY, m1 = -INFINITY, l0 = 0.0f, l1 = 0.0f;
    float o[8][4];
    #pragma unroll
    for (int n = 0; n < 8; n++) { o[n][0] = o[n][1] = o[n][2] = o[n][3] = 0.0f; }

    const int nkt = 2 * qt + 2;
    for (int kt = 0; kt < nkt; kt++) {
        __syncthreads();
        // load K,V tile (tf32-converted)
        #pragma unroll
        for (int i = 0; i < 4; i++) {
            int idx = tid + i * 256;       // 1024 float4 slots = 64 rows x 16
            int r = idx >> 4, c = (idx & 15) * 4;
            size_t grow = (size_t)(kt * 64 + r) * QKV_N;
            float4 kv = *(const float4*)(kb + grow + c);
            float4 vv = *(const float4*)(vb + grow + c);
            kv.x = tf32r(kv.x); kv.y = tf32r(kv.y); kv.z = tf32r(kv.z); kv.w = tf32r(kv.w);
            vv.x = tf32r(vv.x); vv.y = tf32r(vv.y); vv.z = tf32r(vv.z); vv.w = tf32r(vv.w);
            *(float4*)(k_s + r * LDK + c) = kv;
            *(float4*)(v_s + r * LDV + c) = vv;
        }
        __syncthreads();

        // ---- S = Q K^T ----
        float s[8][4];
        #pragma unroll
        for (int n = 0; n < 8; n++) { s[n][0] = s[n][1] = s[n][2] = s[n][3] = 0.0f; }
        const uint32_t* ks_u = (const uint32_t*)k_s;
        #pragma unroll
        for (int kk = 0; kk < 8; kk++) {
            #pragma unroll
            for (int n8 = 0; n8 < 8; n8++) {
                uint32_t b0 = ks_u[(n8 * 8 + lr) * LDK + kk * 8 + lc];
                uint32_t b1 = ks_u[(n8 * 8 + lr) * LDK + kk * 8 + lc + 4];
                mma_tf32(s[n8][0], s[n8][1], s[n8][2], s[n8][3],
                         qf[kk][0], qf[kk][1], qf[kk][2], qf[kk][3], b0, b1);
            }
        }

        // ---- causal mask (only needed on the last two k-tiles of this q-tile) ----
        if (kt >= 2 * qt) {
            const int kbase = kt * 64 + lc * 2;
            #pragma unroll
            for (int n8 = 0; n8 < 8; n8++) {
                int key0 = kbase + n8 * 8;
                int key1 = key0 + 1;
                if (key0 > row0) s[n8][0] = -1e30f;
                if (key1 > row0) s[n8][1] = -1e30f;
                if (key0 > row1) s[n8][2] = -1e30f;
                if (key1 > row1) s[n8][3] = -1e30f;
            }
        }

        // ---- online softmax ----
        float tm0 = -INFINITY, tm1 = -INFINITY;
        #pragma unroll
        for (int n8 = 0; n8 < 8; n8++) {
            tm0 = fmaxf(tm0, fmaxf(s[n8][0], s[n8][1]));
            tm1 = fmaxf(tm1, fmaxf(s[n8][2], s[n8][3]));
        }
        tm0 = fmaxf(tm0, __shfl_xor_sync(0xffffffffu, tm0, 1));
        tm0 = fmaxf(tm0, __shfl_xor_sync(0xffffffffu, tm0, 2));
        tm1 = fmaxf(tm1, __shfl_xor_sync(0xffffffffu, tm1, 1));
        tm1 = fmaxf(tm1, __shfl_xor_sync(0xffffffffu, tm1, 2));
        float nm0 = fmaxf(m0, tm0), nm1 = fmaxf(m1, tm1);
        float a0 = __expf(m0 - nm0), a1 = __expf(m1 - nm1);
        m0 = nm0; m1 = nm1;

        float ts0 = 0.0f, ts1 = 0.0f;
        const int pr0 = (wid * 16 + lr) * LDP + lc * 2;
        const int pr1 = (wid * 16 + lr + 8) * LDP + lc * 2;
        #pragma unroll
        for (int n8 = 0; n8 < 8; n8++) {
            float p0 = __expf(s[n8][0] - nm0);
            float p1 = __expf(s[n8][1] - nm0);
            float p2 = __expf(s[n8][2] - nm1);
            float p3 = __expf(s[n8][3] - nm1);
            ts0 += p0 + p1;
            ts1 += p2 + p3;
            *(float2*)(p_s + pr0 + n8 * 8) = make_float2(tf32r(p0), tf32r(p1));
            *(float2*)(p_s + pr1 + n8 * 8) = make_float2(tf32r(p2), tf32r(p3));
        }
        ts0 += __shfl_xor_sync(0xffffffffu, ts0, 1);
        ts0 += __shfl_xor_sync(0xffffffffu, ts0, 2);
        ts1 += __shfl_xor_sync(0xffffffffu, ts1, 1);
        ts1 += __shfl_xor_sync(0xffffffffu, ts1, 2);
        l0 = l0 * a0 + ts0;
        l1 = l1 * a1 + ts1;
        #pragma unroll
        for (int n8 = 0; n8 < 8; n8++) {
            o[n8][0] *= a0; o[n8][1] *= a0;
            o[n8][2] *= a1; o[n8][3] *= a1;
        }
        __syncwarp();

        // ---- O += P V ----
        const uint32_t* ps_u = (const uint32_t*)p_s;
        const uint32_t* vs_u = (const uint32_t*)v_s;
        #pragma unroll
        for (int kk = 0; kk < 8; kk++) {
            uint32_t pa0 = ps_u[(wid * 16 + lr) * LDP + kk * 8 + lc];
            uint32_t pa1 = ps_u[(wid * 16 + lr + 8) * LDP + kk * 8 + lc];
            uint32_t pa2 = ps_u[(wid * 16 + lr) * LDP + kk * 8 + lc + 4];
            uint32_t pa3 = ps_u[(wid * 16 + lr + 8) * LDP + kk * 8 + lc + 4];
            #pragma unroll
            for (int n8 = 0; n8 < 8; n8++) {
                uint32_t b0 = vs_u[(kk * 8 + lc) * LDV + n8 * 8 + lr];
                uint32_t b1 = vs_u[(kk * 8 + lc + 4) * LDV + n8 * 8 + lr];
                mma_tf32(o[n8][0], o[n8][1], o[n8][2], o[n8][3],
                         pa0, pa1, pa2, pa3, b0, b1);
            }
        }
        __syncwarp();
    }

    // ---- epilogue: normalize and store ----
    float inv0 = 1.0f / l0, inv1 = 1.0f / l1;
    float* z0 = z + (rowbase + row0) * D_MODEL + h * 64 + lc * 2;
    float* z1 = z + (rowbase + row1) * D_MODEL + h * 64 + lc * 2;
    #pragma unroll
    for (int n8 = 0; n8 < 8; n8++) {
        *(float2*)(z0 + n8 * 8) = make_float2(o[n8][0] * inv0, o[n8][1] * inv0);
        *(float2*)(z1 + n8 * 8) = make_float2(o[n8][2] * inv1, o[n8][3] * inv1);
    }
}

// ---------------- launch ----------------
extern "C" void kernel_launch(void* const* d_in, const int* in_sizes, int n_in,
                              void* d_out, int out_size) {
    const float* resid_pre = (const float*)d_in[0];
    const float* WQ   = (const float*)d_in[1];
    const float* bQ   = (const float*)d_in[2];
    const float* WK   = (const float*)d_in[3];
    const float* bK   = (const float*)d_in[4];
    const float* WV   = (const float*)d_in[5];
    const float* bV   = (const float*)d_in[6];
    const float* WO   = (const float*)d_in[7];
    const float* bO   = (const float*)d_in[8];
    const float* ln1w = (const float*)d_in[9];
    const float* ln1b = (const float*)d_in[10];
    const float* ln2w = (const float*)d_in[11];
    const float* ln2b = (const float*)d_in[12];
    const float* Win  = (const float*)d_in[13];
    const float* bin  = (const float*)d_in[14];
    const float* Wout = (const float*)d_in[15];
    const float* bout = (const float*)d_in[16];
    float* out = (float*)d_out;

    float *x1, *qkv, *z, *mid, *x2, *hidden, *wp, *bp;
    cudaGetSymbolAddress((void**)&x1,     g_x1);
    cudaGetSymbolAddress((void**)&qkv,    g_qkv);
    cudaGetSymbolAddress((void**)&z,      g_z);
    cudaGetSymbolAddress((void**)&mid,    g_mid);
    cudaGetSymbolAddress((void**)&x2,     g_x2);
    cudaGetSymbolAddress((void**)&hidden, g_hidden);
    cudaGetSymbolAddress((void**)&wp,     g_wqkv);
    cudaGetSymbolAddress((void**)&bp,     g_bqkv);

    const int SMEM_BN128 = (2 * 128 * 36 + 2 * 32 * 136) * 4;
    const int SMEM_BN64  = (2 * 128 * 36 + 2 * 32 * 72)  * 4;

    cudaFuncSetAttribute(attn_mma_kernel, cudaFuncAttributeMaxDynamicSharedMemorySize, ATTN_SMEM);
    cudaFuncSetAttribute(mma_gemm<128,0,0>, cudaFuncAttributeMaxDynamicSharedMemorySize, SMEM_BN128);
    cudaFuncSetAttribute(mma_gemm<128,1,0>, cudaFuncAttributeMaxDynamicSharedMemorySize, SMEM_BN128);
    cudaFuncSetAttribute(mma_gemm<64,0,1>,  cudaFuncAttributeMaxDynamicSharedMemorySize, SMEM_BN64);

    // 1. repack QKV weights+bias into fused [768, 2304]
    pack_qkv_kernel<<<(D_MODEL * QKV_N + 255) / 256, 256>>>(WQ, WK, WV, bQ, bK, bV, wp, bp);
    // 2. LN1
    ln_kernel<<<ROWS, 256>>>(resid_pre, ln1w, ln1b, x1);
    // 3. fused QKV projection: [4096,768] @ [768,2304]
    mma_gemm<128,0,0><<<dim3(QKV_N / 128, ROWS / 128), 256, SMEM_BN128>>>(
        x1, wp, bp, nullptr, qkv, ROWS, QKV_N, D_MODEL);
    // 4. causal attention -> z [4096, 768]
    attn_mma_kernel<<<dim3(SEQ / 128, BATCH * N_HEADS), 256, ATTN_SMEM>>>(qkv, z);
    // 5. O projection + residual: mid = z @ W_O + b_O + resid_pre
    mma_gemm<64,0,1><<<dim3(D_MODEL / 64, ROWS / 128), 256, SMEM_BN64>>>(
        z, WO, bO, resid_pre, mid, ROWS, D_MODEL, D_MODEL);
    // 6. LN2
    ln_kernel<<<ROWS, 256>>>(mid, ln2w, ln2b, x2);
    // 7. MLP up + gelu: hidden = gelu(x2 @ W_in + b_in)
    mma_gemm<128,1,0><<<dim3(D_MLP / 128, ROWS / 128), 256, SMEM_BN128>>>(
        x2, Win, bin, nullptr, hidden, ROWS, D_MLP, D_MODEL);
    // 8. MLP down + residual: out = hidden @ W_out + b_out + mid
    mma_gemm<64,0,1><<<dim3(D_MODEL / 64, ROWS / 128), 256, SMEM_BN64>>>(
        hidden, Wout, bout, mid, out, ROWS, D_MODEL, D_MLP);
}

// round 5
// speedup vs baseline: 3.4915x; 1.1656x over previous
#include <cuda_runtime.h>
#include <cuda_bf16.h>
#include <math.h>
#include <stdint.h>

// ---------------- problem constants ----------------
#define D_MODEL 768
#define N_HEADS 12
#define D_HEAD  64
#define D_MLP   3072
#define BATCH   2
#define SEQ     2048
#define ROWS    (BATCH*SEQ)          // 4096
#define QKV_N   (3*D_MODEL)          // 2304

// ---------------- device scratch (no runtime alloc allowed) ----------------
__device__ float g_x1    [ROWS * D_MODEL];
__device__ float g_qkv   [ROWS * QKV_N];
__device__ float g_z     [ROWS * D_MODEL];
__device__ float g_mid   [ROWS * D_MODEL];
__device__ float g_x2    [ROWS * D_MODEL];
__device__ float g_hidden[ROWS * D_MLP];
__device__ float g_wqkv  [D_MODEL * QKV_N];     // fused [768][2304], tf32-rounded
__device__ float g_bqkv  [QKV_N];
__device__ float g_woR   [D_MODEL * D_MODEL];   // rounded copies, original layout
__device__ float g_winR  [D_MODEL * D_MLP];
__device__ float g_woutR [D_MLP * D_MODEL];

// ---------------- helpers ----------------
__device__ __forceinline__ uint32_t smem_u32(const void* p) {
    uint32_t a;
    asm("{ .reg .u64 t; cvta.to.shared.u64 t, %1; cvt.u32.u64 %0, t; }" : "=r"(a) : "l"(p));
    return a;
}
__device__ __forceinline__ float fast_tanh(float x) {
    float y; asm("tanh.approx.f32 %0, %1;" : "=f"(y) : "f"(x)); return y;
}
__device__ __forceinline__ float gelu_new_f(float x) {
    const float c = 0.7978845608028654f;
    float x3 = x * x * x;
    return 0.5f * x * (1.0f + fast_tanh(c * (x + 0.044715f * x3)));
}
__device__ __forceinline__ float tf32r(float x) {
    uint32_t u; asm("cvt.rna.tf32.f32 %0, %1;" : "=r"(u) : "f"(x));
    return __uint_as_float(u);
}
__device__ __forceinline__ void mma_tf32(float& c0, float& c1, float& c2, float& c3,
                                         uint32_t a0, uint32_t a1, uint32_t a2, uint32_t a3,
                                         uint32_t b0, uint32_t b1) {
    asm volatile(
        "mma.sync.aligned.m16n8k8.row.col.f32.tf32.tf32.f32 "
        "{%0,%1,%2,%3}, {%4,%5,%6,%7}, {%8,%9}, {%0,%1,%2,%3};\n"
        : "+f"(c0), "+f"(c1), "+f"(c2), "+f"(c3)
        : "r"(a0), "r"(a1), "r"(a2), "r"(a3), "r"(b0), "r"(b1));
}

__device__ __forceinline__ void cp16(uint32_t dst, const void* src) {
    asm volatile("cp.async.cg.shared.global [%0], [%1], 16;" :: "r"(dst), "l"(src));
}
#define CP_COMMIT() asm volatile("cp.async.commit_group;" ::: "memory")
#define CP_WAIT1()  asm volatile("cp.async.wait_group 1;" ::: "memory")
#define CP_WAIT0()  asm volatile("cp.async.wait_group 0;" ::: "memory")

// block-wide sum for 256 threads
__device__ __forceinline__ float block_sum256(float v) {
    __shared__ float red[8];
    __shared__ float total;
    #pragma unroll
    for (int m = 16; m >= 1; m >>= 1) v += __shfl_xor_sync(0xffffffffu, v, m);
    int w = threadIdx.x >> 5;
    if ((threadIdx.x & 31) == 0) red[w] = v;
    __syncthreads();
    if (threadIdx.x < 8) {
        float t = red[threadIdx.x];
        t += __shfl_xor_sync(0xffu, t, 4);
        t += __shfl_xor_sync(0xffu, t, 2);
        t += __shfl_xor_sync(0xffu, t, 1);
        if (threadIdx.x == 0) total = t;
    }
    __syncthreads();
    return total;
}

// ---------------- weight prep -----------------------------------------------------
// fused QKV: Wp[e][3*768], tf32-rounded
__global__ void pack_qkv_kernel(const float* __restrict__ WQ, const float* __restrict__ WK,
                                const float* __restrict__ WV, const float* __restrict__ bQ,
                                const float* __restrict__ bK, const float* __restrict__ bV,
                                float* __restrict__ Wp, float* __restrict__ bp) {
    int idx = blockIdx.x * blockDim.x + threadIdx.x;
    if (idx < D_MODEL * QKV_N) {
        int e = idx / QKV_N;
        int col = idx - e * QKV_N;
        int which = col / D_MODEL;
        int c = col - which * D_MODEL;
        int n = c >> 6;
        int hd = c & 63;
        const float* W = (which == 0) ? WQ : (which == 1) ? WK : WV;
        Wp[idx] = tf32r(W[((size_t)n * D_MODEL + e) * D_HEAD + hd]);
    }
    if (idx < QKV_N) {
        int which = idx / D_MODEL;
        int c = idx - which * D_MODEL;
        const float* bb = (which == 0) ? bQ : (which == 1) ? bK : bV;
        bp[idx] = bb[c];
    }
}

// elementwise tf32 round-copy
__global__ void rnd_copy(const float* __restrict__ src, float* __restrict__ dst, int n4) {
    int i = blockIdx.x * 256 + threadIdx.x;
    if (i < n4) {
        float4 v = *(const float4*)(src + i * 4);
        v.x = tf32r(v.x); v.y = tf32r(v.y); v.z = tf32r(v.z); v.w = tf32r(v.w);
        *(float4*)(dst + i * 4) = v;
    }
}

// ---------------- layernorm (tf32-rounded output) --------------------------------
__global__ void ln_kernel(const float* __restrict__ x, const float* __restrict__ w,
                          const float* __restrict__ b, float* __restrict__ y) {
    int row = blockIdx.x;
    const float* xr = x + (size_t)row * D_MODEL;
    float* yr = y + (size_t)row * D_MODEL;
    int tid = threadIdx.x;
    float v0 = xr[tid], v1 = xr[tid + 256], v2 = xr[tid + 512];
    float s = block_sum256(v0 + v1 + v2);
    float mean = s * (1.0f / D_MODEL);
    float d0 = v0 - mean, d1 = v1 - mean, d2 = v2 - mean;
    float sq = block_sum256(d0 * d0 + d1 * d1 + d2 * d2);
    float rstd = rsqrtf(sq * (1.0f / D_MODEL) + 1e-5f);
    yr[tid]       = tf32r(d0 * rstd * w[tid]       + b[tid]);
    yr[tid + 256] = tf32r(d1 * rstd * w[tid + 256] + b[tid + 256]);
    yr[tid + 512] = tf32r(d2 * rstd * w[tid + 512] + b[tid + 512]);
}

// ---------------- cp.async 3-stage tf32 MMA GEMM ---------------------------------
// C[M,N] = A[M,K] @ B[K,N] + bias (+gelu)(+res)(+tf32 round)
// BM=128, BK=32, BN in {128, 64}. 256 threads, 8 warps (2m x 4n), warp 64 x BN/4.
// Inputs A, B must already be tf32-rounded.
template<int BN, int GELU, int RES, int RND>
__global__ __launch_bounds__(256, 2) void gemm_cp(
        const float* __restrict__ A, const float* __restrict__ B,
        const float* __restrict__ bias, const float* __restrict__ res,
        float* __restrict__ C, int M, int N, int K) {
    constexpr int LDA = 36;          // A smem [128][36]
    constexpr int LDB = BN + 8;      // B smem [32][BN+8]
    constexpr int A_ST = 128 * LDA;
    constexpr int B_ST = 32 * LDB;
    constexpr int STG = A_ST + B_ST;
    constexpr int NT = BN / 32;
    constexpr int TPR = BN / 4;

    extern __shared__ float smem[];
    const uint32_t sb = smem_u32(smem);

    const int tid = threadIdx.x;
    const int lane = tid & 31;
    const int wid = tid >> 5;
    const int lr = lane >> 2;
    const int lc = lane & 3;
    const int warp_m = wid & 1;
    const int warp_n = wid >> 1;
    const int bm = blockIdx.y * 128;
    const int bn = blockIdx.x * BN;

    float acc[4][NT][4];
    #pragma unroll
    for (int i = 0; i < 4; i++)
        #pragma unroll
        for (int j = 0; j < NT; j++)
            #pragma unroll
            for (int u = 0; u < 4; u++) acc[i][j][u] = 0.0f;

    const int nt = K / 32;

    // ---- issue stage s covering k range [bk, bk+32) ----
    auto issue = [&](int s, int bk) {
        uint32_t abase = sb + (uint32_t)(s * STG) * 4u;
        #pragma unroll
        for (int i = 0; i < 4; i++) {
            int idx = tid + i * 256;                 // 1024 chunks
            int rr = idx >> 3, k4 = (idx & 7) * 4;
            cp16(abase + (uint32_t)(rr * LDA + k4) * 4u,
                 A + (size_t)(bm + rr) * K + bk + k4);
        }
        uint32_t bbase = abase + (uint32_t)A_ST * 4u;
        if (BN == 128) {
            #pragma unroll
            for (int i = 0; i < 4; i++) {
                int idx = tid + i * 256;             // 1024 chunks
                int kk = idx >> 5, c4 = (idx & 31) * 4;
                cp16(bbase + (uint32_t)(kk * LDB + c4) * 4u,
                     B + (size_t)(bk + kk) * N + bn + c4);
            }
        } else {
            #pragma unroll
            for (int i = 0; i < 2; i++) {
                int idx = tid + i * 256;             // 512 chunks
                int kk = idx >> 4, c4 = (idx & 15) * 4;
                cp16(bbase + (uint32_t)(kk * LDB + c4) * 4u,
                     B + (size_t)(bk + kk) * N + bn + c4);
            }
        }
    };

    issue(0, 0);  CP_COMMIT();
    issue(1, 32); CP_COMMIT();

    for (int t = 0; t < nt; t++) {
        CP_WAIT1();
        __syncthreads();
        if (t + 2 < nt) issue((t + 2) % 3, (t + 2) * 32);
        CP_COMMIT();

        const int s = t % 3;
        const uint32_t* As_ = (const uint32_t*)(smem + s * STG);
        const uint32_t* Bs_ = (const uint32_t*)(smem + s * STG + A_ST);
        #pragma unroll
        for (int kk = 0; kk < 4; kk++) {
            uint32_t a[4][4];
            uint32_t b[NT][2];
            #pragma unroll
            for (int i = 0; i < 4; i++) {
                int r = warp_m * 64 + i * 16 + lr;
                int c = kk * 8 + lc;
                a[i][0] = As_[r * LDA + c];
                a[i][1] = As_[(r + 8) * LDA + c];
                a[i][2] = As_[r * LDA + c + 4];
                a[i][3] = As_[(r + 8) * LDA + c + 4];
            }
            #pragma unroll
            for (int j = 0; j < NT; j++) {
                int cc = warp_n * TPR + j * 8 + lr;
                b[j][0] = Bs_[(kk * 8 + lc) * LDB + cc];
                b[j][1] = Bs_[(kk * 8 + lc + 4) * LDB + cc];
            }
            #pragma unroll
            for (int i = 0; i < 4; i++)
                #pragma unroll
                for (int j = 0; j < NT; j++)
                    mma_tf32(acc[i][j][0], acc[i][j][1], acc[i][j][2], acc[i][j][3],
                             a[i][0], a[i][1], a[i][2], a[i][3], b[j][0], b[j][1]);
        }
        __syncthreads();
    }
    CP_WAIT0();

    // ---- epilogue ----
    #pragma unroll
    for (int i = 0; i < 4; i++) {
        #pragma unroll
        for (int j = 0; j < NT; j++) {
            int r0 = bm + warp_m * 64 + i * 16 + lr;
            int cc = bn + warp_n * TPR + j * 8 + lc * 2;
            float2 bv = *(const float2*)&bias[cc];
            {
                float o0 = acc[i][j][0] + bv.x;
                float o1 = acc[i][j][1] + bv.y;
                if (GELU) { o0 = gelu_new_f(o0); o1 = gelu_new_f(o1); }
                if (RES) {
                    float2 rv = *(const float2*)&res[(size_t)r0 * N + cc];
                    o0 += rv.x; o1 += rv.y;
                }
                if (RND) { o0 = tf32r(o0); o1 = tf32r(o1); }
                *(float2*)&C[(size_t)r0 * N + cc] = make_float2(o0, o1);
            }
            {
                int r1 = r0 + 8;
                float o0 = acc[i][j][2] + bv.x;
                float o1 = acc[i][j][3] + bv.y;
                if (GELU) { o0 = gelu_new_f(o0); o1 = gelu_new_f(o1); }
                if (RES) {
                    float2 rv = *(const float2*)&res[(size_t)r1 * N + cc];
                    o0 += rv.x; o1 += rv.y;
                }
                if (RND) { o0 = tf32r(o0); o1 = tf32r(o1); }
                *(float2*)&C[(size_t)r1 * N + cc] = make_float2(o0, o1);
            }
        }
    }
}

// ---------------- tf32 MMA flash attention ---------------------------------------
// inputs (qkv) are pre-rounded to tf32 by the QKV GEMM epilogue.
#define LDK 68
#define LDV 72
#define LDP 68
#define ATTN_SMEM ((64*LDK + 64*LDV + 128*LDP) * 4)

__global__ __launch_bounds__(256) void attn_mma_kernel(const float* __restrict__ qkv,
                                                       float* __restrict__ z) {
    const int qt = (SEQ / 128 - 1) - blockIdx.x;
    const int bh = blockIdx.y;
    const int b = bh / N_HEADS;
    const int h = bh - b * N_HEADS;

    extern __shared__ float sm[];
    float* k_s = sm;
    float* v_s = sm + 64 * LDK;
    float* p_s = sm + 64 * LDK + 64 * LDV;

    const int tid = threadIdx.x;
    const int lane = tid & 31;
    const int wid = tid >> 5;
    const int lr = lane >> 2;
    const int lc = lane & 3;

    const size_t rowbase = (size_t)b * SEQ;
    const float* qb = qkv + rowbase * QKV_N + h * 64;
    const float* kb = qb + D_MODEL;
    const float* vb = qb + 2 * D_MODEL;

    #pragma unroll
    for (int i = 0; i < 8; i++) {
        int idx = tid + i * 256;
        int r = idx >> 4, c = (idx & 15) * 4;
        float4 v = *(const float4*)(qb + (size_t)(qt * 128 + r) * QKV_N + c);
        v.x *= 0.125f; v.y *= 0.125f; v.z *= 0.125f; v.w *= 0.125f;   // exact in tf32
        *(float4*)(p_s + r * LDP + c) = v;
    }
    __syncthreads();

    uint32_t qf[8][4];
    {
        int r0 = wid * 16 + lr;
        #pragma unroll
        for (int kk = 0; kk < 8; kk++) {
            int c = kk * 8 + lc;
            qf[kk][0] = __float_as_uint(p_s[r0 * LDP + c]);
            qf[kk][1] = __float_as_uint(p_s[(r0 + 8) * LDP + c]);
            qf[kk][2] = __float_as_uint(p_s[r0 * LDP + c + 4]);
            qf[kk][3] = __float_as_uint(p_s[(r0 + 8) * LDP + c + 4]);
        }
    }
    __syncwarp();

    const int row0 = qt * 128 + wid * 16 + lr;
    const int row1 = row0 + 8;

    float m0 = -INFINITY, m1 = -INFINITY, l0 = 0.0f, l1 = 0.0f;
    float o[8][4];
    #pragma unroll
    for (int n = 0; n < 8; n++) { o[n][0] = o[n][1] = o[n][2] = o[n][3] = 0.0f; }

    const int nkt = 2 * qt + 2;
    for (int kt = 0; kt < nkt; kt++) {
        __syncthreads();
        #pragma unroll
        for (int i = 0; i < 4; i++) {
            int idx = tid + i * 256;
            int r = idx >> 4, c = (idx & 15) * 4;
            size_t grow = (size_t)(kt * 64 + r) * QKV_N;
            *(float4*)(k_s + r * LDK + c) = *(const float4*)(kb + grow + c);
            *(float4*)(v_s + r * LDV + c) = *(const float4*)(vb + grow + c);
        }
        __syncthreads();

        float s[8][4];
        #pragma unroll
        for (int n = 0; n < 8; n++) { s[n][0] = s[n][1] = s[n][2] = s[n][3] = 0.0f; }
        const uint32_t* ks_u = (const uint32_t*)k_s;
        #pragma unroll
        for (int kk = 0; kk < 8; kk++) {
            #pragma unroll
            for (int n8 = 0; n8 < 8; n8++) {
                uint32_t b0 = ks_u[(n8 * 8 + lr) * LDK + kk * 8 + lc];
                uint32_t b1 = ks_u[(n8 * 8 + lr) * LDK + kk * 8 + lc + 4];
                mma_tf32(s[n8][0], s[n8][1], s[n8][2], s[n8][3],
                         qf[kk][0], qf[kk][1], qf[kk][2], qf[kk][3], b0, b1);
            }
        }

        if (kt >= 2 * qt) {
            const int kbase = kt * 64 + lc * 2;
            #pragma unroll
            for (int n8 = 0; n8 < 8; n8++) {
                int key0 = kbase + n8 * 8;
                int key1 = key0 + 1;
                if (key0 > row0) s[n8][0] = -1e30f;
                if (key1 > row0) s[n8][1] = -1e30f;
                if (key0 > row1) s[n8][2] = -1e30f;
                if (key1 > row1) s[n8][3] = -1e30f;
            }
        }

        float tm0 = -INFINITY, tm1 = -INFINITY;
        #pragma unroll
        for (int n8 = 0; n8 < 8; n8++) {
            tm0 = fmaxf(tm0, fmaxf(s[n8][0], s[n8][1]));
            tm1 = fmaxf(tm1, fmaxf(s[n8][2], s[n8][3]));
        }
        tm0 = fmaxf(tm0, __shfl_xor_sync(0xffffffffu, tm0, 1));
        tm0 = fmaxf(tm0, __shfl_xor_sync(0xffffffffu, tm0, 2));
        tm1 = fmaxf(tm1, __shfl_xor_sync(0xffffffffu, tm1, 1));
        tm1 = fmaxf(tm1, __shfl_xor_sync(0xffffffffu, tm1, 2));
        float nm0 = fmaxf(m0, tm0), nm1 = fmaxf(m1, tm1);
        float a0 = __expf(m0 - nm0), a1 = __expf(m1 - nm1);
        m0 = nm0; m1 = nm1;

        float ts0 = 0.0f, ts1 = 0.0f;
        const int pr0 = (wid * 16 + lr) * LDP + lc * 2;
        const int pr1 = (wid * 16 + lr + 8) * LDP + lc * 2;
        #pragma unroll
        for (int n8 = 0; n8 < 8; n8++) {
            float p0 = __expf(s[n8][0] - nm0);
            float p1 = __expf(s[n8][1] - nm0);
            float p2 = __expf(s[n8][2] - nm1);
            float p3 = __expf(s[n8][3] - nm1);
            ts0 += p0 + p1;
            ts1 += p2 + p3;
            *(float2*)(p_s + pr0 + n8 * 8) = make_float2(tf32r(p0), tf32r(p1));
            *(float2*)(p_s + pr1 + n8 * 8) = make_float2(tf32r(p2), tf32r(p3));
        }
        ts0 += __shfl_xor_sync(0xffffffffu, ts0, 1);
        ts0 += __shfl_xor_sync(0xffffffffu, ts0, 2);
        ts1 += __shfl_xor_sync(0xffffffffu, ts1, 1);
        ts1 += __shfl_xor_sync(0xffffffffu, ts1, 2);
        l0 = l0 * a0 + ts0;
        l1 = l1 * a1 + ts1;
        #pragma unroll
        for (int n8 = 0; n8 < 8; n8++) {
            o[n8][0] *= a0; o[n8][1] *= a0;
            o[n8][2] *= a1; o[n8][3] *= a1;
        }
        __syncwarp();

        const uint32_t* ps_u = (const uint32_t*)p_s;
        const uint32_t* vs_u = (const uint32_t*)v_s;
        #pragma unroll
        for (int kk = 0; kk < 8; kk++) {
            uint32_t pa0 = ps_u[(wid * 16 + lr) * LDP + kk * 8 + lc];
            uint32_t pa1 = ps_u[(wid * 16 + lr + 8) * LDP + kk * 8 + lc];
            uint32_t pa2 = ps_u[(wid * 16 + lr) * LDP + kk * 8 + lc + 4];
            uint32_t pa3 = ps_u[(wid * 16 + lr + 8) * LDP + kk * 8 + lc + 4];
            #pragma unroll
            for (int n8 = 0; n8 < 8; n8++) {
                uint32_t b0 = vs_u[(kk * 8 + lc) * LDV + n8 * 8 + lr];
                uint32_t b1 = vs_u[(kk * 8 + lc + 4) * LDV + n8 * 8 + lr];
                mma_tf32(o[n8][0], o[n8][1], o[n8][2], o[n8][3],
                         pa0, pa1, pa2, pa3, b0, b1);
            }
        }
        __syncwarp();
    }

    // z is consumed as GEMM A input -> round to tf32
    float inv0 = 1.0f / l0, inv1 = 1.0f / l1;
    float* z0 = z + (rowbase + row0) * D_MODEL + h * 64 + lc * 2;
    float* z1 = z + (rowbase + row1) * D_MODEL + h * 64 + lc * 2;
    #pragma unroll
    for (int n8 = 0; n8 < 8; n8++) {
        *(float2*)(z0 + n8 * 8) = make_float2(tf32r(o[n8][0] * inv0), tf32r(o[n8][1] * inv0));
        *(float2*)(z1 + n8 * 8) = make_float2(tf32r(o[n8][2] * inv1), tf32r(o[n8][3] * inv1));
    }
}

// ---------------- launch ----------------
extern "C" void kernel_launch(void* const* d_in, const int* in_sizes, int n_in,
                              void* d_out, int out_size) {
    const float* resid_pre = (const float*)d_in[0];
    const float* WQ   = (const float*)d_in[1];
    const float* bQ   = (const float*)d_in[2];
    const float* WK   = (const float*)d_in[3];
    const float* bK   = (const float*)d_in[4];
    const float* WV   = (const float*)d_in[5];
    const float* bV   = (const float*)d_in[6];
    const float* WO   = (const float*)d_in[7];
    const float* bO   = (const float*)d_in[8];
    const float* ln1w = (const float*)d_in[9];
    const float* ln1b = (const float*)d_in[10];
    const float* ln2w = (const float*)d_in[11];
    const float* ln2b = (const float*)d_in[12];
    const float* Win  = (const float*)d_in[13];
    const float* bin  = (const float*)d_in[14];
    const float* Wout = (const float*)d_in[15];
    const float* bout = (const float*)d_in[16];
    float* out = (float*)d_out;

    float *x1, *qkv, *z, *mid, *x2, *hidden, *wp, *bp, *woR, *winR, *woutR;
    cudaGetSymbolAddress((void**)&x1,     g_x1);
    cudaGetSymbolAddress((void**)&qkv,    g_qkv);
    cudaGetSymbolAddress((void**)&z,      g_z);
    cudaGetSymbolAddress((void**)&mid,    g_mid);
    cudaGetSymbolAddress((void**)&x2,     g_x2);
    cudaGetSymbolAddress((void**)&hidden, g_hidden);
    cudaGetSymbolAddress((void**)&wp,     g_wqkv);
    cudaGetSymbolAddress((void**)&bp,     g_bqkv);
    cudaGetSymbolAddress((void**)&woR,    g_woR);
    cudaGetSymbolAddress((void**)&winR,   g_winR);
    cudaGetSymbolAddress((void**)&woutR,  g_woutR);

    // smem sizes: 3 stages of (A 128x36 + B 32x(BN+8)) floats
    const int SMEM_BN128 = 3 * (128 * 36 + 32 * 136) * 4;   // 107520
    const int SMEM_BN64  = 3 * (128 * 36 + 32 * 72)  * 4;   // 82944

    cudaFuncSetAttribute(attn_mma_kernel, cudaFuncAttributeMaxDynamicSharedMemorySize, ATTN_SMEM);
    cudaFuncSetAttribute(gemm_cp<128,0,0,1>, cudaFuncAttributeMaxDynamicSharedMemorySize, SMEM_BN128);
    cudaFuncSetAttribute(gemm_cp<128,1,0,1>, cudaFuncAttributeMaxDynamicSharedMemorySize, SMEM_BN128);
    cudaFuncSetAttribute(gemm_cp<64,0,1,0>,  cudaFuncAttributeMaxDynamicSharedMemorySize, SMEM_BN64);

    // weight prep (tf32 pre-rounding)
    pack_qkv_kernel<<<(D_MODEL * QKV_N + 255) / 256, 256>>>(WQ, WK, WV, bQ, bK, bV, wp, bp);
    rnd_copy<<<(D_MODEL * D_MODEL / 4 + 255) / 256, 256>>>(WO,   woR,   D_MODEL * D_MODEL / 4);
    rnd_copy<<<(D_MODEL * D_MLP   / 4 + 255) / 256, 256>>>(Win,  winR,  D_MODEL * D_MLP / 4);
    rnd_copy<<<(D_MLP   * D_MODEL / 4 + 255) / 256, 256>>>(Wout, woutR, D_MLP * D_MODEL / 4);

    // LN1
    ln_kernel<<<ROWS, 256>>>(resid_pre, ln1w, ln1b, x1);
    // QKV projection (output rounded for attention)
    gemm_cp<128,0,0,1><<<dim3(QKV_N / 128, ROWS / 128), 256, SMEM_BN128>>>(
        x1, wp, bp, nullptr, qkv, ROWS, QKV_N, D_MODEL);
    // attention
    attn_mma_kernel<<<dim3(SEQ / 128, BATCH * N_HEADS), 256, ATTN_SMEM>>>(qkv, z);
    // O projection + residual
    gemm_cp<64,0,1,0><<<dim3(D_MODEL / 64, ROWS / 128), 256, SMEM_BN64>>>(
        z, woR, bO, resid_pre, mid, ROWS, D_MODEL, D_MODEL);
    // LN2
    ln_kernel<<<ROWS, 256>>>(mid, ln2w, ln2b, x2);
    // MLP up + gelu (rounded: feeds next GEMM A side)
    gemm_cp<128,1,0,1><<<dim3(D_MLP / 128, ROWS / 128), 256, SMEM_BN128>>>(
        x2, winR, bin, nullptr, hidden, ROWS, D_MLP, D_MODEL);
    // MLP down + residual
    gemm_cp<64,0,1,0><<<dim3(D_MODEL / 64, ROWS / 128), 256, SMEM_BN64>>>(
        hidden, woutR, bout, mid, out, ROWS, D_MODEL, D_MLP);
}

// round 6
// speedup vs baseline: 5.2735x; 1.5104x over previous
#include <cuda_runtime.h>
#include <cuda_fp16.h>
#include <math.h>
#include <stdint.h>

// ---------------- problem constants ----------------
#define D_MODEL 768
#define N_HEADS 12
#define D_HEAD  64
#define D_MLP   3072
#define BATCH   2
#define SEQ     2048
#define ROWS    (BATCH*SEQ)          // 4096
#define QKV_N   (3*D_MODEL)          // 2304

// ---------------- device scratch ----------------
__device__ __half g_x1h   [ROWS * D_MODEL];
__device__ __half g_qkvh  [ROWS * QKV_N];
__device__ __half g_zh    [ROWS * D_MODEL];
__device__ float  g_mid   [ROWS * D_MODEL];
__device__ __half g_x2h   [ROWS * D_MODEL];
__device__ __half g_hidh  [ROWS * D_MLP];
__device__ __half g_wqkvh [D_MODEL * QKV_N];
__device__ float  g_bqkv  [QKV_N];
__device__ __half g_woh   [D_MODEL * D_MODEL];
__device__ __half g_winh  [D_MODEL * D_MLP];
__device__ __half g_wouth [D_MLP * D_MODEL];

// ---------------- helpers ----------------
__device__ __forceinline__ uint32_t smem_u32(const void* p) {
    uint32_t a;
    asm("{ .reg .u64 t; cvta.to.shared.u64 t, %1; cvt.u32.u64 %0, t; }" : "=r"(a) : "l"(p));
    return a;
}
__device__ __forceinline__ float fast_tanh(float x) {
    float y; asm("tanh.approx.f32 %0, %1;" : "=f"(y) : "f"(x)); return y;
}
__device__ __forceinline__ float gelu_new_f(float x) {
    const float c = 0.7978845608028654f;
    float x3 = x * x * x;
    return 0.5f * x * (1.0f + fast_tanh(c * (x + 0.044715f * x3)));
}
__device__ __forceinline__ float tf32r(float x) {
    uint32_t u; asm("cvt.rna.tf32.f32 %0, %1;" : "=r"(u) : "f"(x));
    return __uint_as_float(u);
}
__device__ __forceinline__ void mma_tf32(float& c0, float& c1, float& c2, float& c3,
                                         uint32_t a0, uint32_t a1, uint32_t a2, uint32_t a3,
                                         uint32_t b0, uint32_t b1) {
    asm volatile(
        "mma.sync.aligned.m16n8k8.row.col.f32.tf32.tf32.f32 "
        "{%0,%1,%2,%3}, {%4,%5,%6,%7}, {%8,%9}, {%0,%1,%2,%3};\n"
        : "+f"(c0), "+f"(c1), "+f"(c2), "+f"(c3)
        : "r"(a0), "r"(a1), "r"(a2), "r"(a3), "r"(b0), "r"(b1));
}
__device__ __forceinline__ void mma_f16(float& c0, float& c1, float& c2, float& c3,
                                        uint32_t a0, uint32_t a1, uint32_t a2, uint32_t a3,
                                        uint32_t b0, uint32_t b1) {
    asm volatile(
        "mma.sync.aligned.m16n8k16.row.col.f32.f16.f16.f32 "
        "{%0,%1,%2,%3}, {%4,%5,%6,%7}, {%8,%9}, {%0,%1,%2,%3};\n"
        : "+f"(c0), "+f"(c1), "+f"(c2), "+f"(c3)
        : "r"(a0), "r"(a1), "r"(a2), "r"(a3), "r"(b0), "r"(b1));
}
__device__ __forceinline__ void ldm_x4(uint32_t& r0, uint32_t& r1, uint32_t& r2, uint32_t& r3,
                                       uint32_t a) {
    asm volatile("ldmatrix.sync.aligned.m8n8.x4.shared.b16 {%0,%1,%2,%3}, [%4];"
                 : "=r"(r0), "=r"(r1), "=r"(r2), "=r"(r3) : "r"(a));
}
__device__ __forceinline__ void ldm_x4t(uint32_t& r0, uint32_t& r1, uint32_t& r2, uint32_t& r3,
                                        uint32_t a) {
    asm volatile("ldmatrix.sync.aligned.m8n8.x4.trans.shared.b16 {%0,%1,%2,%3}, [%4];"
                 : "=r"(r0), "=r"(r1), "=r"(r2), "=r"(r3) : "r"(a));
}
__device__ __forceinline__ void cp16(uint32_t dst, const void* src) {
    asm volatile("cp.async.cg.shared.global [%0], [%1], 16;" :: "r"(dst), "l"(src));
}
#define CP_COMMIT() asm volatile("cp.async.commit_group;" ::: "memory")
#define CP_WAIT1()  asm volatile("cp.async.wait_group 1;" ::: "memory")
#define CP_WAIT0()  asm volatile("cp.async.wait_group 0;" ::: "memory")

__device__ __forceinline__ float block_sum256(float v) {
    __shared__ float red[8];
    __shared__ float total;
    #pragma unroll
    for (int m = 16; m >= 1; m >>= 1) v += __shfl_xor_sync(0xffffffffu, v, m);
    int w = threadIdx.x >> 5;
    if ((threadIdx.x & 31) == 0) red[w] = v;
    __syncthreads();
    if (threadIdx.x < 8) {
        float t = red[threadIdx.x];
        t += __shfl_xor_sync(0xffu, t, 4);
        t += __shfl_xor_sync(0xffu, t, 2);
        t += __shfl_xor_sync(0xffu, t, 1);
        if (threadIdx.x == 0) total = t;
    }
    __syncthreads();
    return total;
}

// ---------------- weight prep -----------------------------------------------------
__global__ void pack_qkv_h(const float* __restrict__ WQ, const float* __restrict__ WK,
                           const float* __restrict__ WV, const float* __restrict__ bQ,
                           const float* __restrict__ bK, const float* __restrict__ bV,
                           __half* __restrict__ Wp, float* __restrict__ bp) {
    int idx = blockIdx.x * blockDim.x + threadIdx.x;
    if (idx < D_MODEL * QKV_N) {
        int e = idx / QKV_N;
        int col = idx - e * QKV_N;
        int which = col / D_MODEL;
        int c = col - which * D_MODEL;
        int n = c >> 6;
        int hd = c & 63;
        const float* W = (which == 0) ? WQ : (which == 1) ? WK : WV;
        Wp[idx] = __float2half_rn(W[((size_t)n * D_MODEL + e) * D_HEAD + hd]);
    }
    if (idx < QKV_N) {
        int which = idx / D_MODEL;
        int c = idx - which * D_MODEL;
        const float* bb = (which == 0) ? bQ : (which == 1) ? bK : bV;
        bp[idx] = bb[c];
    }
}

__global__ void f2h(const float* __restrict__ s, __half* __restrict__ d, int n8) {
    int i = blockIdx.x * 256 + threadIdx.x;
    if (i < n8) {
        float4 v0 = *(const float4*)(s + (size_t)i * 8);
        float4 v1 = *(const float4*)(s + (size_t)i * 8 + 4);
        __half2 h[4];
        h[0] = __floats2half2_rn(v0.x, v0.y);
        h[1] = __floats2half2_rn(v0.z, v0.w);
        h[2] = __floats2half2_rn(v1.x, v1.y);
        h[3] = __floats2half2_rn(v1.z, v1.w);
        *(uint4*)(d + (size_t)i * 8) = *(uint4*)h;
    }
}

// ---------------- layernorm: fp32 in, fp16 out ----------------------------------
__global__ void ln_kernel_h(const float* __restrict__ x, const float* __restrict__ w,
                            const float* __restrict__ b, __half* __restrict__ y) {
    int row = blockIdx.x;
    const float* xr = x + (size_t)row * D_MODEL;
    __half* yr = y + (size_t)row * D_MODEL;
    int tid = threadIdx.x;
    float v0 = xr[tid], v1 = xr[tid + 256], v2 = xr[tid + 512];
    float s = block_sum256(v0 + v1 + v2);
    float mean = s * (1.0f / D_MODEL);
    float d0 = v0 - mean, d1 = v1 - mean, d2 = v2 - mean;
    float sq = block_sum256(d0 * d0 + d1 * d1 + d2 * d2);
    float rstd = rsqrtf(sq * (1.0f / D_MODEL) + 1e-5f);
    yr[tid]       = __float2half_rn(d0 * rstd * w[tid]       + b[tid]);
    yr[tid + 256] = __float2half_rn(d1 * rstd * w[tid + 256] + b[tid + 256]);
    yr[tid + 512] = __float2half_rn(d2 * rstd * w[tid + 512] + b[tid + 512]);
}

// ---------------- fp16 tensor-core GEMM -------------------------------------------
// C[M,N] = A[M,K] @ B[K,N] + bias (+gelu)(+res). A,B fp16; C fp32 or fp16.
// BM=128, BN=128, BK=64. 256 threads, 8 warps (2m x 4n), warp 64x32.
#define GH_STG 32768                  // bytes per stage: A 16KB + B 16KB
#define GH_SMEM (3 * GH_STG)          // 96 KB

template<int GELU, int RES, int OUTH>
__global__ __launch_bounds__(256, 2) void gemm_h(
        const __half* __restrict__ A, const __half* __restrict__ B,
        const float* __restrict__ bias, const float* __restrict__ res,
        void* __restrict__ Cv, int M, int N, int K) {
    extern __shared__ char sm8[];
    const uint32_t sb = smem_u32(sm8);

    const int tid = threadIdx.x;
    const int lane = tid & 31;
    const int wid = tid >> 5;
    const int lr = lane >> 2;
    const int lc = lane & 3;
    const int warp_m = wid & 1;
    const int warp_n = wid >> 1;
    const int bm = blockIdx.y * 128;
    const int bn = blockIdx.x * 128;

    float acc[4][4][4];
    #pragma unroll
    for (int i = 0; i < 4; i++)
        #pragma unroll
        for (int j = 0; j < 4; j++)
            #pragma unroll
            for (int u = 0; u < 4; u++) acc[i][j][u] = 0.0f;

    const int nt = K / 64;

    auto issue = [&](int s, int bk) {
        uint32_t ab = sb + (uint32_t)s * GH_STG;
        #pragma unroll
        for (int i = 0; i < 4; i++) {
            int idx = tid + i * 256;               // 1024 chunks of 8 halves
            int rr = idx >> 3, c = idx & 7;
            cp16(ab + (uint32_t)(rr * 128 + ((c ^ (rr & 7)) * 16)),
                 A + (size_t)(bm + rr) * K + bk + c * 8);
        }
        uint32_t bb = ab + 16384;
        #pragma unroll
        for (int i = 0; i < 4; i++) {
            int idx = tid + i * 256;               // 1024 chunks
            int rr = idx >> 4, c = idx & 15;
            int sc = (c & 8) | ((c ^ rr) & 7);
            cp16(bb + (uint32_t)(rr * 256 + sc * 16),
                 B + (size_t)(bk + rr) * N + bn + c * 8);
        }
    };

    issue(0, 0);  CP_COMMIT();
    issue(1, 64); CP_COMMIT();

    const int j8 = lane >> 3;      // ldmatrix quadrant 0..3
    const int li = lane & 7;

    for (int t = 0; t < nt; t++) {
        CP_WAIT1();
        __syncthreads();
        if (t + 2 < nt) issue((t + 2) % 3, (t + 2) * 64);
        CP_COMMIT();

        const uint32_t Ab = sb + (uint32_t)(t % 3) * GH_STG;
        const uint32_t Bb = Ab + 16384;

        #pragma unroll
        for (int ks = 0; ks < 4; ks++) {
            uint32_t a[4][4];
            #pragma unroll
            for (int i = 0; i < 4; i++) {
                int row = warp_m * 64 + i * 16 + (j8 & 1) * 8 + li;
                int chunk = ks * 2 + (j8 >> 1);
                ldm_x4(a[i][0], a[i][1], a[i][2], a[i][3],
                       Ab + (uint32_t)(row * 128 + ((chunk ^ (row & 7)) * 16)));
            }
            uint32_t b[2][4];
            #pragma unroll
            for (int jn = 0; jn < 2; jn++) {
                int krow = ks * 16 + (j8 & 1) * 8 + li;
                int nch = warp_n * 4 + jn * 2 + (j8 >> 1);
                int sc = (nch & 8) | ((nch ^ krow) & 7);
                ldm_x4t(b[jn][0], b[jn][1], b[jn][2], b[jn][3],
                        Bb + (uint32_t)(krow * 256 + sc * 16));
            }
            #pragma unroll
            for (int i = 0; i < 4; i++)
                #pragma unroll
                for (int n8 = 0; n8 < 4; n8++) {
                    int jn = n8 >> 1, sub = n8 & 1;
                    mma_f16(acc[i][n8][0], acc[i][n8][1], acc[i][n8][2], acc[i][n8][3],
                            a[i][0], a[i][1], a[i][2], a[i][3],
                            b[jn][sub * 2], b[jn][sub * 2 + 1]);
                }
        }
        __syncthreads();
    }
    CP_WAIT0();

    // ---- epilogue ----
    float* Cf = (float*)Cv;
    __half* Ch = (__half*)Cv;
    #pragma unroll
    for (int i = 0; i < 4; i++) {
        #pragma unroll
        for (int n8 = 0; n8 < 4; n8++) {
            int r0 = bm + warp_m * 64 + i * 16 + lr;
            int cc = bn + warp_n * 32 + n8 * 8 + lc * 2;
            float2 bv = *(const float2*)&bias[cc];
            #pragma unroll
            for (int hrow = 0; hrow < 2; hrow++) {
                int r = r0 + hrow * 8;
                float o0 = acc[i][n8][hrow * 2]     + bv.x;
                float o1 = acc[i][n8][hrow * 2 + 1] + bv.y;
                if (GELU) { o0 = gelu_new_f(o0); o1 = gelu_new_f(o1); }
                if (RES) {
                    float2 rv = *(const float2*)&res[(size_t)r * N + cc];
                    o0 += rv.x; o1 += rv.y;
                }
                if (OUTH) {
                    __half2 h = __floats2half2_rn(o0, o1);
                    *(__half2*)&Ch[(size_t)r * N + cc] = h;
                } else {
                    *(float2*)&Cf[(size_t)r * N + cc] = make_float2(o0, o1);
                }
            }
        }
    }
}

// ---------------- tf32 MMA flash attention (half input / half output) -------------
#define LDK 68
#define LDV 72
#define LDP 68
#define ATTN_SMEM ((64*LDK + 64*LDV + 128*LDP) * 4)

__global__ __launch_bounds__(256) void attn_mma_kernel(const __half* __restrict__ qkv,
                                                       __half* __restrict__ z) {
    const int qt = (SEQ / 128 - 1) - blockIdx.x;
    const int bh = blockIdx.y;
    const int b = bh / N_HEADS;
    const int h = bh - b * N_HEADS;

    extern __shared__ float sm[];
    float* k_s = sm;
    float* v_s = sm + 64 * LDK;
    float* p_s = sm + 64 * LDK + 64 * LDV;

    const int tid = threadIdx.x;
    const int lane = tid & 31;
    const int wid = tid >> 5;
    const int lr = lane >> 2;
    const int lc = lane & 3;

    const size_t rowbase = (size_t)b * SEQ;
    const __half* qb = qkv + rowbase * QKV_N + h * 64;
    const __half* kb = qb + D_MODEL;
    const __half* vb = qb + 2 * D_MODEL;

    // stage Q (scaled 1/8, exact) into p_s as fp32
    #pragma unroll
    for (int i = 0; i < 4; i++) {
        int idx = tid + i * 256;                  // 1024 chunks of 8 halves
        int r = idx >> 3, c = (idx & 7) * 8;
        uint4 raw = *(const uint4*)(qb + (size_t)(qt * 128 + r) * QKV_N + c);
        const __half2* hp = (const __half2*)&raw;
        #pragma unroll
        for (int u = 0; u < 4; u++) {
            float2 f = __half22float2(hp[u]);
            p_s[r * LDP + c + u * 2]     = f.x * 0.125f;
            p_s[r * LDP + c + u * 2 + 1] = f.y * 0.125f;
        }
    }
    __syncthreads();

    uint32_t qf[8][4];
    {
        int r0 = wid * 16 + lr;
        #pragma unroll
        for (int kk = 0; kk < 8; kk++) {
            int c = kk * 8 + lc;
            qf[kk][0] = __float_as_uint(p_s[r0 * LDP + c]);
            qf[kk][1] = __float_as_uint(p_s[(r0 + 8) * LDP + c]);
            qf[kk][2] = __float_as_uint(p_s[r0 * LDP + c + 4]);
            qf[kk][3] = __float_as_uint(p_s[(r0 + 8) * LDP + c + 4]);
        }
    }
    __syncwarp();

    const int row0 = qt * 128 + wid * 16 + lr;
    const int row1 = row0 + 8;

    float m0 = -INFINITY, m1 = -INFINITY, l0 = 0.0f, l1 = 0.0f;
    float o[8][4];
    #pragma unroll
    for (int n = 0; n < 8; n++) { o[n][0] = o[n][1] = o[n][2] = o[n][3] = 0.0f; }

    const int nkt = 2 * qt + 2;
    for (int kt = 0; kt < nkt; kt++) {
        __syncthreads();
        #pragma unroll
        for (int i = 0; i < 2; i++) {
            int idx = tid + i * 256;              // 512 chunks of 8 halves
            int r = idx >> 3, c = (idx & 7) * 8;
            size_t grow = (size_t)(kt * 64 + r) * QKV_N;
            uint4 kraw = *(const uint4*)(kb + grow + c);
            uint4 vraw = *(const uint4*)(vb + grow + c);
            const __half2* khp = (const __half2*)&kraw;
            const __half2* vhp = (const __half2*)&vraw;
            #pragma unroll
            for (int u = 0; u < 4; u++) {
                float2 kf = __half22float2(khp[u]);
                float2 vf = __half22float2(vhp[u]);
                k_s[r * LDK + c + u * 2]     = kf.x;
                k_s[r * LDK + c + u * 2 + 1] = kf.y;
                v_s[r * LDV + c + u * 2]     = vf.x;
                v_s[r * LDV + c + u * 2 + 1] = vf.y;
            }
        }
        __syncthreads();

        float s[8][4];
        #pragma unroll
        for (int n = 0; n < 8; n++) { s[n][0] = s[n][1] = s[n][2] = s[n][3] = 0.0f; }
        const uint32_t* ks_u = (const uint32_t*)k_s;
        #pragma unroll
        for (int kk = 0; kk < 8; kk++) {
            #pragma unroll
            for (int n8 = 0; n8 < 8; n8++) {
                uint32_t b0 = ks_u[(n8 * 8 + lr) * LDK + kk * 8 + lc];
                uint32_t b1 = ks_u[(n8 * 8 + lr) * LDK + kk * 8 + lc + 4];
                mma_tf32(s[n8][0], s[n8][1], s[n8][2], s[n8][3],
                         qf[kk][0], qf[kk][1], qf[kk][2], qf[kk][3], b0, b1);
            }
        }

        if (kt >= 2 * qt) {
            const int kbase = kt * 64 + lc * 2;
            #pragma unroll
            for (int n8 = 0; n8 < 8; n8++) {
                int key0 = kbase + n8 * 8;
                int key1 = key0 + 1;
                if (key0 > row0) s[n8][0] = -1e30f;
                if (key1 > row0) s[n8][1] = -1e30f;
                if (key0 > row1) s[n8][2] = -1e30f;
                if (key1 > row1) s[n8][3] = -1e30f;
            }
        }

        float tm0 = -INFINITY, tm1 = -INFINITY;
        #pragma unroll
        for (int n8 = 0; n8 < 8; n8++) {
            tm0 = fmaxf(tm0, fmaxf(s[n8][0], s[n8][1]));
            tm1 = fmaxf(tm1, fmaxf(s[n8][2], s[n8][3]));
        }
        tm0 = fmaxf(tm0, __shfl_xor_sync(0xffffffffu, tm0, 1));
        tm0 = fmaxf(tm0, __shfl_xor_sync(0xffffffffu, tm0, 2));
        tm1 = fmaxf(tm1, __shfl_xor_sync(0xffffffffu, tm1, 1));
        tm1 = fmaxf(tm1, __shfl_xor_sync(0xffffffffu, tm1, 2));
        float nm0 = fmaxf(m0, tm0), nm1 = fmaxf(m1, tm1);
        float a0 = __expf(m0 - nm0), a1 = __expf(m1 - nm1);
        m0 = nm0; m1 = nm1;

        float ts0 = 0.0f, ts1 = 0.0f;
        const int pr0 = (wid * 16 + lr) * LDP + lc * 2;
        const int pr1 = (wid * 16 + lr + 8) * LDP + lc * 2;
        #pragma unroll
        for (int n8 = 0; n8 < 8; n8++) {
            float p0 = __expf(s[n8][0] - nm0);
            float p1 = __expf(s[n8][1] - nm0);
            float p2 = __expf(s[n8][2] - nm1);
            float p3 = __expf(s[n8][3] - nm1);
            ts0 += p0 + p1;
            ts1 += p2 + p3;
            *(float2*)(p_s + pr0 + n8 * 8) = make_float2(tf32r(p0), tf32r(p1));
            *(float2*)(p_s + pr1 + n8 * 8) = make_float2(tf32r(p2), tf32r(p3));
        }
        ts0 += __shfl_xor_sync(0xffffffffu, ts0, 1);
        ts0 += __shfl_xor_sync(0xffffffffu, ts0, 2);
        ts1 += __shfl_xor_sync(0xffffffffu, ts1, 1);
        ts1 += __shfl_xor_sync(0xffffffffu, ts1, 2);
        l0 = l0 * a0 + ts0;
        l1 = l1 * a1 + ts1;
        #pragma unroll
        for (int n8 = 0; n8 < 8; n8++) {
            o[n8][0] *= a0; o[n8][1] *= a0;
            o[n8][2] *= a1; o[n8][3] *= a1;
        }
        __syncwarp();

        const uint32_t* ps_u = (const uint32_t*)p_s;
        const uint32_t* vs_u = (const uint32_t*)v_s;
        #pragma unroll
        for (int kk = 0; kk < 8; kk++) {
            uint32_t pa0 = ps_u[(wid * 16 + lr) * LDP + kk * 8 + lc];
            uint32_t pa1 = ps_u[(wid * 16 + lr + 8) * LDP + kk * 8 + lc];
            uint32_t pa2 = ps_u[(wid * 16 + lr) * LDP + kk * 8 + lc + 4];
            uint32_t pa3 = ps_u[(wid * 16 + lr + 8) * LDP + kk * 8 + lc + 4];
            #pragma unroll
            for (int n8 = 0; n8 < 8; n8++) {
                uint32_t b0 = vs_u[(kk * 8 + lc) * LDV + n8 * 8 + lr];
                uint32_t b1 = vs_u[(kk * 8 + lc + 4) * LDV + n8 * 8 + lr];
                mma_tf32(o[n8][0], o[n8][1], o[n8][2], o[n8][3],
                         pa0, pa1, pa2, pa3, b0, b1);
            }
        }
        __syncwarp();
    }

    float inv0 = 1.0f / l0, inv1 = 1.0f / l1;
    __half* z0 = z + (rowbase + row0) * D_MODEL + h * 64 + lc * 2;
    __half* z1 = z + (rowbase + row1) * D_MODEL + h * 64 + lc * 2;
    #pragma unroll
    for (int n8 = 0; n8 < 8; n8++) {
        *(__half2*)(z0 + n8 * 8) = __floats2half2_rn(o[n8][0] * inv0, o[n8][1] * inv0);
        *(__half2*)(z1 + n8 * 8) = __floats2half2_rn(o[n8][2] * inv1, o[n8][3] * inv1);
    }
}

// ---------------- launch ----------------
extern "C" void kernel_launch(void* const* d_in, const int* in_sizes, int n_in,
                              void* d_out, int out_size) {
    const float* resid_pre = (const float*)d_in[0];
    const float* WQ   = (const float*)d_in[1];
    const float* bQ   = (const float*)d_in[2];
    const float* WK   = (const float*)d_in[3];
    const float* bK   = (const float*)d_in[4];
    const float* WV   = (const float*)d_in[5];
    const float* bV   = (const float*)d_in[6];
    const float* WO   = (const float*)d_in[7];
    const float* bO   = (const float*)d_in[8];
    const float* ln1w = (const float*)d_in[9];
    const float* ln1b = (const float*)d_in[10];
    const float* ln2w = (const float*)d_in[11];
    const float* ln2b = (const float*)d_in[12];
    const float* Win  = (const float*)d_in[13];
    const float* bin  = (const float*)d_in[14];
    const float* Wout = (const float*)d_in[15];
    const float* bout = (const float*)d_in[16];
    float* out = (float*)d_out;

    __half *x1h, *qkvh, *zh, *x2h, *hidh, *wqkvh, *woh, *winh, *wouth;
    float *mid, *bp;
    cudaGetSymbolAddress((void**)&x1h,    g_x1h);
    cudaGetSymbolAddress((void**)&qkvh,   g_qkvh);
    cudaGetSymbolAddress((void**)&zh,     g_zh);
    cudaGetSymbolAddress((void**)&mid,    g_mid);
    cudaGetSymbolAddress((void**)&x2h,    g_x2h);
    cudaGetSymbolAddress((void**)&hidh,   g_hidh);
    cudaGetSymbolAddress((void**)&wqkvh,  g_wqkvh);
    cudaGetSymbolAddress((void**)&bp,     g_bqkv);
    cudaGetSymbolAddress((void**)&woh,    g_woh);
    cudaGetSymbolAddress((void**)&winh,   g_winh);
    cudaGetSymbolAddress((void**)&wouth,  g_wouth);

    cudaFuncSetAttribute(attn_mma_kernel, cudaFuncAttributeMaxDynamicSharedMemorySize, ATTN_SMEM);
    cudaFuncSetAttribute(gemm_h<0,0,1>, cudaFuncAttributeMaxDynamicSharedMemorySize, GH_SMEM);
    cudaFuncSetAttribute(gemm_h<0,1,0>, cudaFuncAttributeMaxDynamicSharedMemorySize, GH_SMEM);
    cudaFuncSetAttribute(gemm_h<1,0,1>, cudaFuncAttributeMaxDynamicSharedMemorySize, GH_SMEM);

    // weight prep
    pack_qkv_h<<<(D_MODEL * QKV_N + 255) / 256, 256>>>(WQ, WK, WV, bQ, bK, bV, wqkvh, bp);
    f2h<<<(D_MODEL * D_MODEL / 8 + 255) / 256, 256>>>(WO,   woh,   D_MODEL * D_MODEL / 8);
    f2h<<<(D_MODEL * D_MLP   / 8 + 255) / 256, 256>>>(Win,  winh,  D_MODEL * D_MLP / 8);
    f2h<<<(D_MLP   * D_MODEL / 8 + 255) / 256, 256>>>(Wout, wouth, D_MLP * D_MODEL / 8);

    // LN1 -> half
    ln_kernel_h<<<ROWS, 256>>>(resid_pre, ln1w, ln1b, x1h);
    // QKV projection -> half
    gemm_h<0,0,1><<<dim3(QKV_N / 128, ROWS / 128), 256, GH_SMEM>>>(
        x1h, wqkvh, bp, nullptr, qkvh, ROWS, QKV_N, D_MODEL);
    // attention -> half z
    attn_mma_kernel<<<dim3(SEQ / 128, BATCH * N_HEADS), 256, ATTN_SMEM>>>(qkvh, zh);
    // O projection + residual -> float mid
    gemm_h<0,1,0><<<dim3(D_MODEL / 128, ROWS / 128), 256, GH_SMEM>>>(
        zh, woh, bO, resid_pre, mid, ROWS, D_MODEL, D_MODEL);
    // LN2 -> half
    ln_kernel_h<<<ROWS, 256>>>(mid, ln2w, ln2b, x2h);
    // MLP up + gelu -> half
    gemm_h<1,0,1><<<dim3(D_MLP / 128, ROWS / 128), 256, GH_SMEM>>>(
        x2h, winh, bin, nullptr, hidh, ROWS, D_MLP, D_MODEL);
    // MLP down + residual -> float out
    gemm_h<0,1,0><<<dim3(D_MODEL / 128, ROWS / 128), 256, GH_SMEM>>>(
        hidh, wouth, bout, mid, out, ROWS, D_MODEL, D_MLP);
}